// round 8
// baseline (speedup 1.0000x reference)
#include <cuda_runtime.h>
#include <cuda_fp16.h>
#include <cstdint>
#include <cstddef>

#define NPTS 300000

static constexpr int kV0 = 60000, kV1 = 30000, kV2 = 15000, kV3 = 120000;
static constexpr int kTOTV = kV0 + kV1 + kV2 + kV3;            // 225000
static constexpr int kOFF0 = 0, kOFF1 = 60000, kOFF2 = 90000, kOFF3 = 105000;
static constexpr int kVIN = kV0 + kV1 + kV2;                   // 105000

// ---------------- scratch (static device globals; no allocation) -------------
__device__ float4 g_sums[kTOTV];            // per-voxel point sums (x,y,z,w)
__device__ float  g_counts[kTOTV];          // per-voxel counts
__device__ int    g_offsets[kTOTV];         // per-scale exclusive scan of counts
__device__ int    g_cursor[kTOTV];          // fill cursors
__device__ int    g_plist[4 * NPTS];        // CSR point lists, segmented per scale
__device__ __half g_sf1[(size_t)NPTS * 192];   // [N, 3*64] AVFE sf features (half)
__device__ __half g_vmax[(size_t)kVIN * 64];   // per-voxel max of sf, scales 0-2
__device__ __half g_sf2h[(size_t)NPTS * 128];  // [N,128] AVFEO sf (half)
__device__ __half g_wt[128 * 384];          // W_pt2 transposed to [n][k], half

__device__ __forceinline__ float relu(float x) { return fmaxf(x, 0.f); }

__device__ __forceinline__ void mma16816(float* c, uint32_t a0, uint32_t a1,
                                         uint32_t a2, uint32_t a3,
                                         uint32_t b0, uint32_t b1) {
    asm volatile(
        "mma.sync.aligned.m16n8k16.row.col.f32.f16.f16.f32 "
        "{%0,%1,%2,%3}, {%4,%5,%6,%7}, {%8,%9}, {%0,%1,%2,%3};"
        : "+f"(c[0]), "+f"(c[1]), "+f"(c[2]), "+f"(c[3])
        : "r"(a0), "r"(a1), "r"(a2), "r"(a3), "r"(b0), "r"(b1));
}

// ---------------- K0: zero scratch ------------------------------------------
__global__ void k_zero() {
    int i = blockIdx.x * blockDim.x + threadIdx.x;
    if (i < kTOTV * 4) ((float*)g_sums)[i] = 0.f;
    if (i < kTOTV) { g_counts[i] = 0.f; g_cursor[i] = 0; }
}

// ---------------- K1: segment sums + counts (all 4 scales) ------------------
__global__ void k_accum(const float4* __restrict__ pts, const int* __restrict__ pvs) {
    int p = blockIdx.x * blockDim.x + threadIdx.x;
    if (p >= NPTS) return;
    float4 q = pts[p];
    const int off[4] = {kOFF0, kOFF1, kOFF2, kOFF3};
#pragma unroll
    for (int i = 0; i < 4; i++) {
        int b = off[i] + pvs[i * NPTS + p];
        atomicAdd(&g_sums[b].x, q.x);
        atomicAdd(&g_sums[b].y, q.y);
        atomicAdd(&g_sums[b].z, q.z);
        atomicAdd(&g_sums[b].w, q.w);
        atomicAdd(&g_counts[b], 1.f);
    }
}

// ---------------- K2: per-scale exclusive scan of counts -> offsets ---------
__global__ void k_scan() {
    __shared__ int sh[1024];
    const int Vs[4]  = {kV0, kV1, kV2, kV3};
    const int off[4] = {kOFF0, kOFF1, kOFF2, kOFF3};
    int s = blockIdx.x;
    int V = Vs[s], base = off[s];
    int chunk = (V + 1023) / 1024;
    int lo = threadIdx.x * chunk;
    int hi = min(lo + chunk, V);
    int sum = 0;
    for (int v = lo; v < hi; v++) sum += (int)g_counts[base + v];
    sh[threadIdx.x] = sum;
    __syncthreads();
    if (threadIdx.x == 0) {
        int run = 0;
        for (int t = 0; t < 1024; t++) { int x = sh[t]; sh[t] = run; run += x; }
    }
    __syncthreads();
    int run = sh[threadIdx.x];
    for (int v = lo; v < hi; v++) { g_offsets[base + v] = run; run += (int)g_counts[base + v]; }
}

// ---------------- K3: fill CSR point lists ----------------------------------
__global__ void k_fill(const int* __restrict__ pvs) {
    int p = blockIdx.x * blockDim.x + threadIdx.x;
    if (p >= NPTS) return;
    const int off[4] = {kOFF0, kOFF1, kOFF2, kOFF3};
#pragma unroll
    for (int i = 0; i < 4; i++) {
        int b = off[i] + pvs[i * NPTS + p];
        int pos = atomicAdd(&g_cursor[b], 1);
        g_plist[i * NPTS + g_offsets[b] + pos] = p;
    }
}

// ---------------- K3b: transpose W_pt2 -> [n][k] half -----------------------
__global__ void k_prepw(const float* __restrict__ Wpt2) {
    int idx = blockIdx.x * blockDim.x + threadIdx.x;
    if (idx >= 128 * 384) return;
    int n = idx / 384, k = idx % 384;
    g_wt[idx] = __float2half(Wpt2[k * 128 + n]);
}

// ---------------- K4: AVFE point stage (3 scales), warp per point -----------
__global__ __launch_bounds__(256) void k_avfe1(
    const float4* __restrict__ pts, const float* __restrict__ Wp1,
    const float* __restrict__ Wa1, const int* __restrict__ pvs) {
    __shared__ float sWp[256];   // [4][64]
    __shared__ float sWa[512];   // [8][64]
    for (int j = threadIdx.x; j < 256; j += 256) sWp[j] = Wp1[j];
    for (int j = threadIdx.x; j < 512; j += 256) sWa[j] = Wa1[j];
    __syncthreads();

    int w = blockIdx.x * 8 + (threadIdx.x >> 5);
    if (w >= NPTS) return;
    int lane = threadIdx.x & 31;
    int c0 = lane, c1 = lane + 32;
    float4 q = pts[w];
    float pf0 = relu(q.x * sWp[c0] + q.y * sWp[64 + c0] + q.z * sWp[128 + c0] + q.w * sWp[192 + c0]);
    float pf1 = relu(q.x * sWp[c1] + q.y * sWp[64 + c1] + q.z * sWp[128 + c1] + q.w * sWp[192 + c1]);
    size_t fb = (size_t)w * 192;
    const int off[3] = {kOFF0, kOFF1, kOFF2};
#pragma unroll
    for (int i = 0; i < 3; i++) {
        int b = off[i] + pvs[i * NPTS + w];
        float inv = 1.0f / fmaxf(g_counts[b], 1.0f);
        float4 s = g_sums[b];
        float m0 = s.x * inv, m1 = s.y * inv, m2 = s.z * inv, m3 = s.w * inv;
        float a0 = q.x - m0, a1 = q.y - m1, a2 = q.z - m2, a3 = q.w;
        float af0 = a0 * sWa[c0] + a1 * sWa[64 + c0] + a2 * sWa[128 + c0] + a3 * sWa[192 + c0]
                  + m0 * sWa[256 + c0] + m1 * sWa[320 + c0] + m2 * sWa[384 + c0] + m3 * sWa[448 + c0];
        float af1 = a0 * sWa[c1] + a1 * sWa[64 + c1] + a2 * sWa[128 + c1] + a3 * sWa[192 + c1]
                  + m0 * sWa[256 + c1] + m1 * sWa[320 + c1] + m2 * sWa[384 + c1] + m3 * sWa[448 + c1];
        g_sf1[fb + i * 64 + c0] = __float2half(pf0 * relu(af0));
        g_sf1[fb + i * 64 + c1] = __float2half(pf1 * relu(af1));
    }
}

// ------ K5: segment-max (scales 0-2) -> g_vmax[V,64], half2 + MLP=4 ---------
__global__ __launch_bounds__(256) void k_max1() {
    int w = blockIdx.x * 8 + (threadIdx.x >> 5);
    if (w >= kVIN) return;
    int lane = threadIdx.x & 31;
    int i;
    if (w < kV0)            i = 0;
    else if (w < kV0 + kV1) i = 1;
    else                    i = 2;
    int b = w;                       // packed global voxel index, scales 0-2
    int o = g_offsets[b];
    int cnt = (int)g_counts[b];
    const int* pl = &g_plist[i * NPTS + o];
    const __half2 z = __floats2half2_rn(0.f, 0.f);   // sf >= 0 always
    __half2 m0 = z, m1 = z, m2 = z, m3 = z;
    int t = 0;
    for (; t + 4 <= cnt; t += 4) {
        int pa = pl[t], pb = pl[t + 1], pc = pl[t + 2], pd = pl[t + 3];
        __half2 va = *(const __half2*)&g_sf1[(size_t)pa * 192 + i * 64 + 2 * lane];
        __half2 vb = *(const __half2*)&g_sf1[(size_t)pb * 192 + i * 64 + 2 * lane];
        __half2 vc = *(const __half2*)&g_sf1[(size_t)pc * 192 + i * 64 + 2 * lane];
        __half2 vd = *(const __half2*)&g_sf1[(size_t)pd * 192 + i * 64 + 2 * lane];
        m0 = __hmax2(m0, va); m1 = __hmax2(m1, vb);
        m2 = __hmax2(m2, vc); m3 = __hmax2(m3, vd);
    }
    for (; t < cnt; t++) {
        int pa = pl[t];
        m0 = __hmax2(m0, *(const __half2*)&g_sf1[(size_t)pa * 192 + i * 64 + 2 * lane]);
    }
    m0 = __hmax2(m0, m1);
    m2 = __hmax2(m2, m3);
    m0 = __hmax2(m0, m2);
    *(__half2*)&g_vmax[(size_t)b * 64 + 2 * lane] = m0;
}

// ------ K6: HMMA GEMM  sf2 = relu(final@W_pt2) * relu(att2@W_att2) ----------
// R6-proven structure (scalar LDS fragments): CTA 128 rows x N=128, 8 warps;
// warp 16 rows x 128 cols (16 n-tiles m16n8k16). K=384 in 12 chunks of 32;
// smem stride 40 halves. A-tile: sub 0,1 -> g_sf1 stream; sub 2,3 -> g_vmax.
static constexpr int GSTRIDE = 40;

__global__ __launch_bounds__(256) void k_gemm_mma(
    const float4* __restrict__ pts, const float* __restrict__ Watt2,
    const int* __restrict__ pvs) {
    __shared__ __align__(16) __half sA[128 * GSTRIDE];
    __shared__ __align__(16) __half sB[128 * GSTRIDE];
    __shared__ float sWs[1024];
    __shared__ int   svox[3][128];

    int tid = threadIdx.x;
    int warp = tid >> 5, lane = tid & 31;
    int p0 = blockIdx.x * 128;
    for (int j = tid; j < 1024; j += 256) sWs[j] = Watt2[j];
    for (int j = tid; j < 384; j += 256) {
        int i = j >> 7, r = j & 127;
        int p = p0 + r;
        svox[i][r] = (p < NPTS) ? pvs[i * NPTS + p] : 0;
    }
    const int voff[3] = {kOFF0, kOFF1, kOFF2};

    float acc[16][4];
#pragma unroll
    for (int nt = 0; nt < 16; nt++)
#pragma unroll
        for (int j = 0; j < 4; j++) acc[nt][j] = 0.f;

    for (int c = 0; c < 12; c++) {
        int i_s = c >> 2, sub = c & 3;
#pragma unroll
        for (int it = 0; it < 2; it++) {
            int idx = it * 256 + tid;
            int row = idx >> 2, seg = idx & 3;
            int gp = p0 + row;
            uint4 av = {0, 0, 0, 0};
            if (sub < 2) {
                if (gp < NPTS)
                    av = *(const uint4*)&g_sf1[(size_t)gp * 192 + i_s * 64 + sub * 32 + seg * 8];
            } else {
                int vox = svox[i_s][row];
                av = *(const uint4*)&g_vmax[((size_t)(voff[i_s] + vox)) * 64 + (sub - 2) * 32 + seg * 8];
            }
            *(uint4*)&sA[row * GSTRIDE + seg * 8] = av;
            uint4 bv = *(const uint4*)&g_wt[row * 384 + c * 32 + seg * 8];
            *(uint4*)&sB[row * GSTRIDE + seg * 8] = bv;
        }
        __syncthreads();
#pragma unroll
        for (int ks = 0; ks < 2; ks++) {
            int ar = warp * 16 + (lane >> 2);
            int ac = ks * 16 + 2 * (lane & 3);
            uint32_t a0 = *(const uint32_t*)&sA[ar * GSTRIDE + ac];
            uint32_t a1 = *(const uint32_t*)&sA[(ar + 8) * GSTRIDE + ac];
            uint32_t a2 = *(const uint32_t*)&sA[ar * GSTRIDE + ac + 8];
            uint32_t a3 = *(const uint32_t*)&sA[(ar + 8) * GSTRIDE + ac + 8];
#pragma unroll
            for (int nt = 0; nt < 16; nt++) {
                int br = nt * 8 + (lane >> 2);
                int bc = ks * 16 + 2 * (lane & 3);
                uint32_t b0 = *(const uint32_t*)&sB[br * GSTRIDE + bc];
                uint32_t b1 = *(const uint32_t*)&sB[br * GSTRIDE + bc + 8];
                mma16816(acc[nt], a0, a1, a2, a3, b0, b1);
            }
        }
        __syncthreads();
    }

    // Epilogue: attention-2 + relu + half2 sf2 write
    int ra = p0 + warp * 16 + (lane >> 2);
    int rb = ra + 8;
#pragma unroll
    for (int rsel = 0; rsel < 2; rsel++) {
        int p = rsel ? rb : ra;
        if (p >= NPTS) continue;
        int b = kOFF3 + pvs[3 * NPTS + p];
        float inv = 1.0f / fmaxf(g_counts[b], 1.0f);
        float4 s = g_sums[b];
        float4 q = pts[p];
        float m0 = s.x * inv, m1 = s.y * inv, m2 = s.z * inv, m3 = s.w * inv;
        float a0 = q.x - m0, a1 = q.y - m1, a2 = q.z - m2, a3 = q.w;
#pragma unroll
        for (int nt = 0; nt < 16; nt++) {
            int c = nt * 8 + 2 * (lane & 3);
            float af0 = a0 * sWs[c] + a1 * sWs[128 + c] + a2 * sWs[256 + c]
                      + a3 * sWs[384 + c] + m0 * sWs[512 + c] + m1 * sWs[640 + c]
                      + m2 * sWs[768 + c] + m3 * sWs[896 + c];
            int c1 = c + 1;
            float af1 = a0 * sWs[c1] + a1 * sWs[128 + c1] + a2 * sWs[256 + c1]
                      + a3 * sWs[384 + c1] + m0 * sWs[512 + c1] + m1 * sWs[640 + c1]
                      + m2 * sWs[768 + c1] + m3 * sWs[896 + c1];
            float v0 = relu(acc[nt][rsel * 2 + 0]) * relu(af0);
            float v1 = relu(acc[nt][rsel * 2 + 1]) * relu(af1);
            *(__half2*)&g_sf2h[(size_t)p * 128 + c] = __floats2half2_rn(v0, v1);
        }
    }
}

// ------ K7: segment-max over sf2 (scale 3) + scatter, half2 + MLP=2 ---------
__global__ __launch_bounds__(256) void k_maxout(
    const int* __restrict__ vfs, float* __restrict__ out) {
    int w = blockIdx.x * 8 + (threadIdx.x >> 5);
    if (w >= kV3) return;
    int lane = threadIdx.x & 31;
    int b = kOFF3 + w;
    int o = g_offsets[b];
    int cnt = (int)g_counts[b];
    const int* pl = &g_plist[3 * NPTS + o];
    const __half2 z = __floats2half2_rn(0.f, 0.f);
    __half2 ma0 = z, ma1 = z, mb0 = z, mb1 = z;
    int t = 0;
    for (; t + 2 <= cnt; t += 2) {
        int pa = pl[t], pb = pl[t + 1];
        const __half2* rowa = (const __half2*)&g_sf2h[(size_t)pa * 128];
        const __half2* rowb = (const __half2*)&g_sf2h[(size_t)pb * 128];
        __half2 ya0 = rowa[lane], ya1 = rowa[lane + 32];
        __half2 yb0 = rowb[lane], yb1 = rowb[lane + 32];
        ma0 = __hmax2(ma0, ya0); ma1 = __hmax2(ma1, ya1);
        mb0 = __hmax2(mb0, yb0); mb1 = __hmax2(mb1, yb1);
    }
    if (t < cnt) {
        int pa = pl[t];
        const __half2* rowa = (const __half2*)&g_sf2h[(size_t)pa * 128];
        ma0 = __hmax2(ma0, rowa[lane]);
        ma1 = __hmax2(ma1, rowa[lane + 32]);
    }
    ma0 = __hmax2(ma0, mb0);
    ma1 = __hmax2(ma1, mb1);
    int vb = vfs[w * 3 + 0], vy = vfs[w * 3 + 1], vx = vfs[w * 3 + 2];
    size_t ob = (size_t)vb * 128 * 262144 + (size_t)vy * 512 + vx;
    out[ob + (size_t)(2 * lane)      * 262144] = __low2float(ma0);
    out[ob + (size_t)(2 * lane + 1)  * 262144] = __high2float(ma0);
    out[ob + (size_t)(64 + 2 * lane) * 262144] = __low2float(ma1);
    out[ob + (size_t)(65 + 2 * lane) * 262144] = __high2float(ma1);
}

// ---------------------------------------------------------------------------
extern "C" void kernel_launch(void* const* d_in, const int* in_sizes, int n_in,
                              void* d_out, int out_size) {
    const float4* pts   = (const float4*)d_in[0];
    const float*  Wp1   = (const float*)d_in[1];
    const float*  Wa1   = (const float*)d_in[2];
    const float*  Wpt2  = (const float*)d_in[3];
    const float*  Watt2 = (const float*)d_in[4];
    const int*    pvs   = (const int*)d_in[5];
    const int*    vfs   = (const int*)d_in[6];
    float*        out   = (float*)d_out;

    cudaMemsetAsync(d_out, 0, (size_t)out_size * sizeof(float), 0);

    k_zero<<<(kTOTV * 4 + 255) / 256, 256>>>();
    k_accum<<<(NPTS + 255) / 256, 256>>>(pts, pvs);
    k_scan<<<4, 1024>>>();
    k_fill<<<(NPTS + 255) / 256, 256>>>(pvs);
    k_prepw<<<(128 * 384 + 255) / 256, 256>>>(Wpt2);
    k_avfe1<<<(NPTS + 7) / 8, 256>>>(pts, Wp1, Wa1, pvs);
    k_max1<<<(kVIN + 7) / 8, 256>>>();
    k_gemm_mma<<<(NPTS + 127) / 128, 256>>>(pts, Watt2, pvs);
    k_maxout<<<(kV3 + 7) / 8, 256>>>(vfs, out);
}

// round 9
// speedup vs baseline: 1.3669x; 1.3669x over previous
#include <cuda_runtime.h>
#include <cuda_fp16.h>
#include <cstdint>
#include <cstddef>

#define NPTS 300000

static constexpr int kV0 = 60000, kV1 = 30000, kV2 = 15000, kV3 = 120000;
static constexpr int kTOTV = kV0 + kV1 + kV2 + kV3;            // 225000
static constexpr int kOFF0 = 0, kOFF1 = 60000, kOFF2 = 90000, kOFF3 = 105000;
static constexpr int kVIN = kV0 + kV1 + kV2;                   // 105000
static constexpr int kB = 2, kH = 512, kW = 512, kHW = kH * kW;

// ---------------- scratch (static device globals; no allocation) -------------
__device__ float4 g_sums[kTOTV];            // per-voxel point sums (x,y,z,w)
__device__ float  g_counts[kTOTV];          // per-voxel counts
__device__ int    g_offsets[kTOTV];         // per-scale exclusive scan of counts
__device__ int    g_cursor[kTOTV];          // fill cursors
__device__ int    g_plist[4 * NPTS];        // CSR point lists, segmented per scale
__device__ __half g_sf1[(size_t)NPTS * 192];   // [N, 3*64] AVFE sf features (half)
__device__ __half g_vmax[(size_t)kVIN * 64];   // per-voxel max of sf, scales 0-2
__device__ __half g_sf2h[(size_t)NPTS * 128];  // [N,128] AVFEO sf (half)
__device__ __half g_wt[128 * 384];          // W_pt2 transposed to [n][k], half
__device__ float  g_omax[(size_t)kV3 * 128];   // per-voxel output max (coalesced)
__device__ int    g_occmap[kB * kHW];       // dense cell -> scale-3 voxel (-1 empty)

__device__ __forceinline__ float relu(float x) { return fmaxf(x, 0.f); }

__device__ __forceinline__ void mma16816(float* c, uint32_t a0, uint32_t a1,
                                         uint32_t a2, uint32_t a3,
                                         uint32_t b0, uint32_t b1) {
    asm volatile(
        "mma.sync.aligned.m16n8k16.row.col.f32.f16.f16.f32 "
        "{%0,%1,%2,%3}, {%4,%5,%6,%7}, {%8,%9}, {%0,%1,%2,%3};"
        : "+f"(c[0]), "+f"(c[1]), "+f"(c[2]), "+f"(c[3])
        : "r"(a0), "r"(a1), "r"(a2), "r"(a3), "r"(b0), "r"(b1));
}

// ---------------- K0: zero scratch ------------------------------------------
__global__ void k_zero() {
    int i = blockIdx.x * blockDim.x + threadIdx.x;
    if (i < kTOTV * 4) ((float*)g_sums)[i] = 0.f;
    if (i < kTOTV) { g_counts[i] = 0.f; g_cursor[i] = 0; }
}

// ---------------- K0b: occmap init + fill -----------------------------------
__global__ void k_occzero() {
    int i = blockIdx.x * blockDim.x + threadIdx.x;
    if (i < kB * kHW) g_occmap[i] = -1;
}
__global__ void k_occfill(const int* __restrict__ vfs) {
    int w = blockIdx.x * blockDim.x + threadIdx.x;
    if (w >= kV3) return;
    int vb = vfs[w * 3 + 0], vy = vfs[w * 3 + 1], vx = vfs[w * 3 + 2];
    g_occmap[vb * kHW + vy * kW + vx] = w;
}

// ---------------- K1: segment sums + counts (all 4 scales) ------------------
__global__ void k_accum(const float4* __restrict__ pts, const int* __restrict__ pvs) {
    int p = blockIdx.x * blockDim.x + threadIdx.x;
    if (p >= NPTS) return;
    float4 q = pts[p];
    const int off[4] = {kOFF0, kOFF1, kOFF2, kOFF3};
#pragma unroll
    for (int i = 0; i < 4; i++) {
        int b = off[i] + pvs[i * NPTS + p];
        atomicAdd(&g_sums[b].x, q.x);
        atomicAdd(&g_sums[b].y, q.y);
        atomicAdd(&g_sums[b].z, q.z);
        atomicAdd(&g_sums[b].w, q.w);
        atomicAdd(&g_counts[b], 1.f);
    }
}

// ---------------- K2: per-scale exclusive scan of counts -> offsets ---------
__global__ void k_scan() {
    __shared__ int sh[1024];
    const int Vs[4]  = {kV0, kV1, kV2, kV3};
    const int off[4] = {kOFF0, kOFF1, kOFF2, kOFF3};
    int s = blockIdx.x;
    int V = Vs[s], base = off[s];
    int chunk = (V + 1023) / 1024;
    int lo = threadIdx.x * chunk;
    int hi = min(lo + chunk, V);
    int sum = 0;
    for (int v = lo; v < hi; v++) sum += (int)g_counts[base + v];
    sh[threadIdx.x] = sum;
    __syncthreads();
    if (threadIdx.x == 0) {
        int run = 0;
        for (int t = 0; t < 1024; t++) { int x = sh[t]; sh[t] = run; run += x; }
    }
    __syncthreads();
    int run = sh[threadIdx.x];
    for (int v = lo; v < hi; v++) { g_offsets[base + v] = run; run += (int)g_counts[base + v]; }
}

// ---------------- K3: fill CSR point lists ----------------------------------
__global__ void k_fill(const int* __restrict__ pvs) {
    int p = blockIdx.x * blockDim.x + threadIdx.x;
    if (p >= NPTS) return;
    const int off[4] = {kOFF0, kOFF1, kOFF2, kOFF3};
#pragma unroll
    for (int i = 0; i < 4; i++) {
        int b = off[i] + pvs[i * NPTS + p];
        int pos = atomicAdd(&g_cursor[b], 1);
        g_plist[i * NPTS + g_offsets[b] + pos] = p;
    }
}

// ---------------- K3b: transpose W_pt2 -> [n][k] half -----------------------
__global__ void k_prepw(const float* __restrict__ Wpt2) {
    int idx = blockIdx.x * blockDim.x + threadIdx.x;
    if (idx >= 128 * 384) return;
    int n = idx / 384, k = idx % 384;
    g_wt[idx] = __float2half(Wpt2[k * 128 + n]);
}

// ---------------- K4: AVFE point stage (3 scales), warp per point -----------
__global__ __launch_bounds__(256) void k_avfe1(
    const float4* __restrict__ pts, const float* __restrict__ Wp1,
    const float* __restrict__ Wa1, const int* __restrict__ pvs) {
    __shared__ float sWp[256];   // [4][64]
    __shared__ float sWa[512];   // [8][64]
    for (int j = threadIdx.x; j < 256; j += 256) sWp[j] = Wp1[j];
    for (int j = threadIdx.x; j < 512; j += 256) sWa[j] = Wa1[j];
    __syncthreads();

    int w = blockIdx.x * 8 + (threadIdx.x >> 5);
    if (w >= NPTS) return;
    int lane = threadIdx.x & 31;
    int c0 = lane, c1 = lane + 32;
    float4 q = pts[w];
    float pf0 = relu(q.x * sWp[c0] + q.y * sWp[64 + c0] + q.z * sWp[128 + c0] + q.w * sWp[192 + c0]);
    float pf1 = relu(q.x * sWp[c1] + q.y * sWp[64 + c1] + q.z * sWp[128 + c1] + q.w * sWp[192 + c1]);
    size_t fb = (size_t)w * 192;
    const int off[3] = {kOFF0, kOFF1, kOFF2};
#pragma unroll
    for (int i = 0; i < 3; i++) {
        int b = off[i] + pvs[i * NPTS + w];
        float inv = 1.0f / fmaxf(g_counts[b], 1.0f);
        float4 s = g_sums[b];
        float m0 = s.x * inv, m1 = s.y * inv, m2 = s.z * inv, m3 = s.w * inv;
        float a0 = q.x - m0, a1 = q.y - m1, a2 = q.z - m2, a3 = q.w;
        float af0 = a0 * sWa[c0] + a1 * sWa[64 + c0] + a2 * sWa[128 + c0] + a3 * sWa[192 + c0]
                  + m0 * sWa[256 + c0] + m1 * sWa[320 + c0] + m2 * sWa[384 + c0] + m3 * sWa[448 + c0];
        float af1 = a0 * sWa[c1] + a1 * sWa[64 + c1] + a2 * sWa[128 + c1] + a3 * sWa[192 + c1]
                  + m0 * sWa[256 + c1] + m1 * sWa[320 + c1] + m2 * sWa[384 + c1] + m3 * sWa[448 + c1];
        g_sf1[fb + i * 64 + c0] = __float2half(pf0 * relu(af0));
        g_sf1[fb + i * 64 + c1] = __float2half(pf1 * relu(af1));
    }
}

// ------ K5: segment-max (scales 0-2) -> g_vmax[V,64] (R6-proven body) -------
__global__ __launch_bounds__(256) void k_max1() {
    int w = blockIdx.x * 8 + (threadIdx.x >> 5);
    if (w >= kVIN) return;
    int lane = threadIdx.x & 31;
    int i;
    if (w < kV0)            i = 0;
    else if (w < kV0 + kV1) i = 1;
    else                    i = 2;
    int b = w;                       // packed global voxel index, scales 0-2
    int o = g_offsets[b];
    int cnt = (int)g_counts[b];
    const int* pl = &g_plist[i * NPTS + o];
    float m0 = 0.f, m1 = 0.f;        // sf >= 0 always (product of relus)
    for (int t = 0; t < cnt; t++) {
        int pt = pl[t];
        size_t fb = (size_t)pt * 192 + i * 64;
        m0 = fmaxf(m0, __half2float(g_sf1[fb + lane]));
        m1 = fmaxf(m1, __half2float(g_sf1[fb + lane + 32]));
    }
    g_vmax[(size_t)b * 64 + lane]      = __float2half(m0);
    g_vmax[(size_t)b * 64 + lane + 32] = __float2half(m1);
}

// ------ K6: HMMA GEMM  sf2 = relu(final@W_pt2) * relu(att2@W_att2) ----------
// R6-proven structure (scalar LDS fragments): CTA 128 rows x N=128, 8 warps;
// warp 16 rows x 128 cols (16 n-tiles m16n8k16). K=384 in 12 chunks of 32;
// smem stride 40 halves. A-tile: sub 0,1 -> g_sf1 stream; sub 2,3 -> g_vmax.
static constexpr int GSTRIDE = 40;

__global__ __launch_bounds__(256) void k_gemm_mma(
    const float4* __restrict__ pts, const float* __restrict__ Watt2,
    const int* __restrict__ pvs) {
    __shared__ __align__(16) __half sA[128 * GSTRIDE];
    __shared__ __align__(16) __half sB[128 * GSTRIDE];
    __shared__ float sWs[1024];
    __shared__ int   svox[3][128];

    int tid = threadIdx.x;
    int warp = tid >> 5, lane = tid & 31;
    int p0 = blockIdx.x * 128;
    for (int j = tid; j < 1024; j += 256) sWs[j] = Watt2[j];
    for (int j = tid; j < 384; j += 256) {
        int i = j >> 7, r = j & 127;
        int p = p0 + r;
        svox[i][r] = (p < NPTS) ? pvs[i * NPTS + p] : 0;
    }
    const int voff[3] = {kOFF0, kOFF1, kOFF2};

    float acc[16][4];
#pragma unroll
    for (int nt = 0; nt < 16; nt++)
#pragma unroll
        for (int j = 0; j < 4; j++) acc[nt][j] = 0.f;

    for (int c = 0; c < 12; c++) {
        int i_s = c >> 2, sub = c & 3;
#pragma unroll
        for (int it = 0; it < 2; it++) {
            int idx = it * 256 + tid;
            int row = idx >> 2, seg = idx & 3;
            int gp = p0 + row;
            uint4 av = {0, 0, 0, 0};
            if (sub < 2) {
                if (gp < NPTS)
                    av = *(const uint4*)&g_sf1[(size_t)gp * 192 + i_s * 64 + sub * 32 + seg * 8];
            } else {
                int vox = svox[i_s][row];
                av = *(const uint4*)&g_vmax[((size_t)(voff[i_s] + vox)) * 64 + (sub - 2) * 32 + seg * 8];
            }
            *(uint4*)&sA[row * GSTRIDE + seg * 8] = av;
            uint4 bv = *(const uint4*)&g_wt[row * 384 + c * 32 + seg * 8];
            *(uint4*)&sB[row * GSTRIDE + seg * 8] = bv;
        }
        __syncthreads();
#pragma unroll
        for (int ks = 0; ks < 2; ks++) {
            int ar = warp * 16 + (lane >> 2);
            int ac = ks * 16 + 2 * (lane & 3);
            uint32_t a0 = *(const uint32_t*)&sA[ar * GSTRIDE + ac];
            uint32_t a1 = *(const uint32_t*)&sA[(ar + 8) * GSTRIDE + ac];
            uint32_t a2 = *(const uint32_t*)&sA[ar * GSTRIDE + ac + 8];
            uint32_t a3 = *(const uint32_t*)&sA[(ar + 8) * GSTRIDE + ac + 8];
#pragma unroll
            for (int nt = 0; nt < 16; nt++) {
                int br = nt * 8 + (lane >> 2);
                int bc = ks * 16 + 2 * (lane & 3);
                uint32_t b0 = *(const uint32_t*)&sB[br * GSTRIDE + bc];
                uint32_t b1 = *(const uint32_t*)&sB[br * GSTRIDE + bc + 8];
                mma16816(acc[nt], a0, a1, a2, a3, b0, b1);
            }
        }
        __syncthreads();
    }

    // Epilogue: attention-2 + relu + half2 sf2 write
    int ra = p0 + warp * 16 + (lane >> 2);
    int rb = ra + 8;
#pragma unroll
    for (int rsel = 0; rsel < 2; rsel++) {
        int p = rsel ? rb : ra;
        if (p >= NPTS) continue;
        int b = kOFF3 + pvs[3 * NPTS + p];
        float inv = 1.0f / fmaxf(g_counts[b], 1.0f);
        float4 s = g_sums[b];
        float4 q = pts[p];
        float m0 = s.x * inv, m1 = s.y * inv, m2 = s.z * inv, m3 = s.w * inv;
        float a0 = q.x - m0, a1 = q.y - m1, a2 = q.z - m2, a3 = q.w;
#pragma unroll
        for (int nt = 0; nt < 16; nt++) {
            int c = nt * 8 + 2 * (lane & 3);
            float af0 = a0 * sWs[c] + a1 * sWs[128 + c] + a2 * sWs[256 + c]
                      + a3 * sWs[384 + c] + m0 * sWs[512 + c] + m1 * sWs[640 + c]
                      + m2 * sWs[768 + c] + m3 * sWs[896 + c];
            int c1 = c + 1;
            float af1 = a0 * sWs[c1] + a1 * sWs[128 + c1] + a2 * sWs[256 + c1]
                      + a3 * sWs[384 + c1] + m0 * sWs[512 + c1] + m1 * sWs[640 + c1]
                      + m2 * sWs[768 + c1] + m3 * sWs[896 + c1];
            float v0 = relu(acc[nt][rsel * 2 + 0]) * relu(af0);
            float v1 = relu(acc[nt][rsel * 2 + 1]) * relu(af1);
            *(__half2*)&g_sf2h[(size_t)p * 128 + c] = __floats2half2_rn(v0, v1);
        }
    }
}

// ------ K7: segment-max over sf2 (scale 3) -> g_omax (coalesced write) ------
__global__ __launch_bounds__(256) void k_vmax3() {
    int w = blockIdx.x * 8 + (threadIdx.x >> 5);
    if (w >= kV3) return;
    int lane = threadIdx.x & 31;
    int b = kOFF3 + w;
    int o = g_offsets[b];
    int cnt = (int)g_counts[b];
    const int* pl = &g_plist[3 * NPTS + o];
    float m0 = 0.f, m1 = 0.f, m2 = 0.f, m3 = 0.f;
    for (int t = 0; t < cnt; t++) {
        int pt = pl[t];
        size_t sb = (size_t)pt * 128 + lane;
        m0 = fmaxf(m0, __half2float(g_sf2h[sb]));
        m1 = fmaxf(m1, __half2float(g_sf2h[sb + 32]));
        m2 = fmaxf(m2, __half2float(g_sf2h[sb + 64]));
        m3 = fmaxf(m3, __half2float(g_sf2h[sb + 96]));
    }
    size_t ob = (size_t)w * 128;
    g_omax[ob + lane]      = m0;
    g_omax[ob + lane + 32] = m1;
    g_omax[ob + lane + 64] = m2;
    g_omax[ob + lane + 96] = m3;
}

// ------ K8: dense output writer, one (b,y) row per block --------------------
// Stages occupied voxels' omax rows in smem (stride 129 floats, conflict-
// light), then writes all 128 channels x 512 x fully coalesced. No memset.
static constexpr int DCAP = 200;
static constexpr int DSM_BYTES = 512 * 4 + DCAP * 4 + 16 + DCAP * 129 * 4;

__global__ __launch_bounds__(256) void k_dense(float* __restrict__ out) {
    extern __shared__ char dsm[];
    int*   s_sidx = (int*)dsm;                       // [512]
    int*   s_vox  = (int*)(dsm + 2048);              // [DCAP]
    int*   s_cnt  = (int*)(dsm + 2048 + DCAP * 4);   // [1]
    float* s_om   = (float*)(dsm + 2048 + DCAP * 4 + 16); // [DCAP*129]

    int row = blockIdx.x;            // 0..kB*kH-1
    int b = row >> 9, y = row & 511;
    int tid = threadIdx.x;
    if (tid == 0) *s_cnt = 0;
    __syncthreads();

    int cellbase = b * kHW + y * kW;
    for (int x = tid; x < 512; x += 256) {
        int v = g_occmap[cellbase + x];
        int code = -1;
        if (v >= 0) {
            int slot = atomicAdd(s_cnt, 1);
            if (slot < DCAP) { s_vox[slot] = v; code = slot; }
            else             { code = -2 - v; }   // overflow: direct gather
        }
        s_sidx[x] = code;
    }
    __syncthreads();
    int cnt = min(*s_cnt, DCAP);
    for (int j = tid; j < cnt * 128; j += 256) {
        int slot = j >> 7, c = j & 127;
        s_om[slot * 129 + c] = g_omax[(size_t)s_vox[slot] * 128 + c];
    }
    __syncthreads();

    size_t outbase = ((size_t)b * 128) * kHW + (size_t)y * kW;
#pragma unroll 4
    for (int c = 0; c < 128; c++) {
        size_t ob = outbase + (size_t)c * kHW;
        for (int x = tid; x < 512; x += 256) {
            int code = s_sidx[x];
            float val = 0.f;
            if (code >= 0)       val = s_om[code * 129 + c];
            else if (code <= -2) val = g_omax[(size_t)(-2 - code) * 128 + c];
            out[ob + x] = val;
        }
    }
}

// ---------------------------------------------------------------------------
extern "C" void kernel_launch(void* const* d_in, const int* in_sizes, int n_in,
                              void* d_out, int out_size) {
    const float4* pts   = (const float4*)d_in[0];
    const float*  Wp1   = (const float*)d_in[1];
    const float*  Wa1   = (const float*)d_in[2];
    const float*  Wpt2  = (const float*)d_in[3];
    const float*  Watt2 = (const float*)d_in[4];
    const int*    pvs   = (const int*)d_in[5];
    const int*    vfs   = (const int*)d_in[6];
    float*        out   = (float*)d_out;

    cudaFuncSetAttribute(k_dense, cudaFuncAttributeMaxDynamicSharedMemorySize,
                         DSM_BYTES);

    k_zero<<<(kTOTV * 4 + 255) / 256, 256>>>();
    k_occzero<<<(kB * kHW + 255) / 256, 256>>>();
    k_occfill<<<(kV3 + 255) / 256, 256>>>(vfs);
    k_accum<<<(NPTS + 255) / 256, 256>>>(pts, pvs);
    k_scan<<<4, 1024>>>();
    k_fill<<<(NPTS + 255) / 256, 256>>>(pvs);
    k_prepw<<<(128 * 384 + 255) / 256, 256>>>(Wpt2);
    k_avfe1<<<(NPTS + 7) / 8, 256>>>(pts, Wp1, Wa1, pvs);
    k_max1<<<(kVIN + 7) / 8, 256>>>();
    k_gemm_mma<<<(NPTS + 127) / 128, 256>>>(pts, Watt2, pvs);
    k_vmax3<<<(kV3 + 7) / 8, 256>>>();
    k_dense<<<kB * kH, 256, DSM_BYTES>>>(out);
}

// round 10
// speedup vs baseline: 1.4256x; 1.0429x over previous
#include <cuda_runtime.h>
#include <cuda_fp16.h>
#include <cstdint>
#include <cstddef>

#define NPTS 300000

static constexpr int kV0 = 60000, kV1 = 30000, kV2 = 15000, kV3 = 120000;
static constexpr int kTOTV = kV0 + kV1 + kV2 + kV3;            // 225000
static constexpr int kOFF0 = 0, kOFF1 = 60000, kOFF2 = 90000, kOFF3 = 105000;
static constexpr int kVIN = kV0 + kV1 + kV2;                   // 105000
static constexpr int kB = 2, kH = 512, kW = 512, kHW = kH * kW;

// ---------------- scratch (static device globals; no allocation) -------------
__device__ float4 g_sums[kTOTV];            // per-voxel point sums (x,y,z,w)
__device__ float  g_counts[kTOTV];          // per-voxel counts
__device__ int    g_offsets[kTOTV];         // per-scale exclusive scan of counts
__device__ int    g_cursor[kTOTV];          // fill cursors
__device__ int    g_plist[4 * NPTS];        // CSR point lists, segmented per scale
__device__ __half g_sf1[(size_t)NPTS * 192];   // [N, 3*64] AVFE sf features (half)
__device__ __half g_vmax[(size_t)kVIN * 64];   // per-voxel max of sf, scales 0-2
__device__ __half g_sf2h[(size_t)NPTS * 128];  // [N,128] AVFEO sf (half)
__device__ __half g_wt[128 * 384];          // W_pt2 transposed to [n][k], half
__device__ float  g_omax[(size_t)kV3 * 128];   // per-voxel output max (coalesced)
__device__ int    g_occmap[kB * kHW];       // dense cell -> scale-3 voxel (-1 empty)

__device__ __forceinline__ float relu(float x) { return fmaxf(x, 0.f); }

__device__ __forceinline__ uint32_t smem_u32(const void* p) {
    uint32_t a;
    asm("{ .reg .u64 t; cvta.to.shared.u64 t, %1; cvt.u32.u64 %0, t; }"
        : "=r"(a) : "l"(p));
    return a;
}

__device__ __forceinline__ void cp_async16(uint32_t saddr, const void* gaddr,
                                           int src_bytes) {
    asm volatile("cp.async.cg.shared.global [%0], [%1], 16, %2;"
                 :: "r"(saddr), "l"(gaddr), "r"(src_bytes));
}
#define CP_COMMIT() asm volatile("cp.async.commit_group;" ::: "memory")
#define CP_WAIT(n)  asm volatile("cp.async.wait_group %0;" :: "n"(n) : "memory")

__device__ __forceinline__ void mma16816(float* c, uint32_t a0, uint32_t a1,
                                         uint32_t a2, uint32_t a3,
                                         uint32_t b0, uint32_t b1) {
    asm volatile(
        "mma.sync.aligned.m16n8k16.row.col.f32.f16.f16.f32 "
        "{%0,%1,%2,%3}, {%4,%5,%6,%7}, {%8,%9}, {%0,%1,%2,%3};"
        : "+f"(c[0]), "+f"(c[1]), "+f"(c[2]), "+f"(c[3])
        : "r"(a0), "r"(a1), "r"(a2), "r"(a3), "r"(b0), "r"(b1));
}

// ---------------- K0: zero scratch ------------------------------------------
__global__ void k_zero() {
    int i = blockIdx.x * blockDim.x + threadIdx.x;
    if (i < kTOTV * 4) ((float*)g_sums)[i] = 0.f;
    if (i < kTOTV) { g_counts[i] = 0.f; g_cursor[i] = 0; }
}

// ---------------- K0b: occmap init + fill -----------------------------------
__global__ void k_occzero() {
    int i = blockIdx.x * blockDim.x + threadIdx.x;
    if (i < kB * kHW) g_occmap[i] = -1;
}
__global__ void k_occfill(const int* __restrict__ vfs) {
    int w = blockIdx.x * blockDim.x + threadIdx.x;
    if (w >= kV3) return;
    int vb = vfs[w * 3 + 0], vy = vfs[w * 3 + 1], vx = vfs[w * 3 + 2];
    g_occmap[vb * kHW + vy * kW + vx] = w;
}

// ---------------- K1: segment sums + counts (all 4 scales) ------------------
__global__ void k_accum(const float4* __restrict__ pts, const int* __restrict__ pvs) {
    int p = blockIdx.x * blockDim.x + threadIdx.x;
    if (p >= NPTS) return;
    float4 q = pts[p];
    const int off[4] = {kOFF0, kOFF1, kOFF2, kOFF3};
#pragma unroll
    for (int i = 0; i < 4; i++) {
        int b = off[i] + pvs[i * NPTS + p];
        atomicAdd(&g_sums[b].x, q.x);
        atomicAdd(&g_sums[b].y, q.y);
        atomicAdd(&g_sums[b].z, q.z);
        atomicAdd(&g_sums[b].w, q.w);
        atomicAdd(&g_counts[b], 1.f);
    }
}

// ---------------- K2: per-scale exclusive scan of counts -> offsets ---------
__global__ void k_scan() {
    __shared__ int sh[1024];
    const int Vs[4]  = {kV0, kV1, kV2, kV3};
    const int off[4] = {kOFF0, kOFF1, kOFF2, kOFF3};
    int s = blockIdx.x;
    int V = Vs[s], base = off[s];
    int chunk = (V + 1023) / 1024;
    int lo = threadIdx.x * chunk;
    int hi = min(lo + chunk, V);
    int sum = 0;
    for (int v = lo; v < hi; v++) sum += (int)g_counts[base + v];
    sh[threadIdx.x] = sum;
    __syncthreads();
    if (threadIdx.x == 0) {
        int run = 0;
        for (int t = 0; t < 1024; t++) { int x = sh[t]; sh[t] = run; run += x; }
    }
    __syncthreads();
    int run = sh[threadIdx.x];
    for (int v = lo; v < hi; v++) { g_offsets[base + v] = run; run += (int)g_counts[base + v]; }
}

// ---------------- K3: fill CSR point lists ----------------------------------
__global__ void k_fill(const int* __restrict__ pvs) {
    int p = blockIdx.x * blockDim.x + threadIdx.x;
    if (p >= NPTS) return;
    const int off[4] = {kOFF0, kOFF1, kOFF2, kOFF3};
#pragma unroll
    for (int i = 0; i < 4; i++) {
        int b = off[i] + pvs[i * NPTS + p];
        int pos = atomicAdd(&g_cursor[b], 1);
        g_plist[i * NPTS + g_offsets[b] + pos] = p;
    }
}

// ---------------- K3b: transpose W_pt2 -> [n][k] half -----------------------
__global__ void k_prepw(const float* __restrict__ Wpt2) {
    int idx = blockIdx.x * blockDim.x + threadIdx.x;
    if (idx >= 128 * 384) return;
    int n = idx / 384, k = idx % 384;
    g_wt[idx] = __float2half(Wpt2[k * 128 + n]);
}

// ---------------- K4: AVFE point stage (3 scales), warp per point -----------
__global__ __launch_bounds__(256) void k_avfe1(
    const float4* __restrict__ pts, const float* __restrict__ Wp1,
    const float* __restrict__ Wa1, const int* __restrict__ pvs) {
    __shared__ float sWp[256];   // [4][64]
    __shared__ float sWa[512];   // [8][64]
    for (int j = threadIdx.x; j < 256; j += 256) sWp[j] = Wp1[j];
    for (int j = threadIdx.x; j < 512; j += 256) sWa[j] = Wa1[j];
    __syncthreads();

    int w = blockIdx.x * 8 + (threadIdx.x >> 5);
    if (w >= NPTS) return;
    int lane = threadIdx.x & 31;
    int c0 = lane, c1 = lane + 32;
    float4 q = pts[w];
    float pf0 = relu(q.x * sWp[c0] + q.y * sWp[64 + c0] + q.z * sWp[128 + c0] + q.w * sWp[192 + c0]);
    float pf1 = relu(q.x * sWp[c1] + q.y * sWp[64 + c1] + q.z * sWp[128 + c1] + q.w * sWp[192 + c1]);
    size_t fb = (size_t)w * 192;
    const int off[3] = {kOFF0, kOFF1, kOFF2};
#pragma unroll
    for (int i = 0; i < 3; i++) {
        int b = off[i] + pvs[i * NPTS + w];
        float inv = 1.0f / fmaxf(g_counts[b], 1.0f);
        float4 s = g_sums[b];
        float m0 = s.x * inv, m1 = s.y * inv, m2 = s.z * inv, m3 = s.w * inv;
        float a0 = q.x - m0, a1 = q.y - m1, a2 = q.z - m2, a3 = q.w;
        float af0 = a0 * sWa[c0] + a1 * sWa[64 + c0] + a2 * sWa[128 + c0] + a3 * sWa[192 + c0]
                  + m0 * sWa[256 + c0] + m1 * sWa[320 + c0] + m2 * sWa[384 + c0] + m3 * sWa[448 + c0];
        float af1 = a0 * sWa[c1] + a1 * sWa[64 + c1] + a2 * sWa[128 + c1] + a3 * sWa[192 + c1]
                  + m0 * sWa[256 + c1] + m1 * sWa[320 + c1] + m2 * sWa[384 + c1] + m3 * sWa[448 + c1];
        g_sf1[fb + i * 64 + c0] = __float2half(pf0 * relu(af0));
        g_sf1[fb + i * 64 + c1] = __float2half(pf1 * relu(af1));
    }
}

// ------ K5: segment-max (scales 0-2) -> g_vmax[V,64] (R6-proven body) -------
__global__ __launch_bounds__(256) void k_max1() {
    int w = blockIdx.x * 8 + (threadIdx.x >> 5);
    if (w >= kVIN) return;
    int lane = threadIdx.x & 31;
    int i;
    if (w < kV0)            i = 0;
    else if (w < kV0 + kV1) i = 1;
    else                    i = 2;
    int b = w;                       // packed global voxel index, scales 0-2
    int o = g_offsets[b];
    int cnt = (int)g_counts[b];
    const int* pl = &g_plist[i * NPTS + o];
    float m0 = 0.f, m1 = 0.f;        // sf >= 0 always (product of relus)
    for (int t = 0; t < cnt; t++) {
        int pt = pl[t];
        size_t fb = (size_t)pt * 192 + i * 64;
        m0 = fmaxf(m0, __half2float(g_sf1[fb + lane]));
        m1 = fmaxf(m1, __half2float(g_sf1[fb + lane + 32]));
    }
    g_vmax[(size_t)b * 64 + lane]      = __float2half(m0);
    g_vmax[(size_t)b * 64 + lane + 32] = __float2half(m1);
}

// ------ K6: HMMA GEMM  sf2 = relu(final@W_pt2) * relu(att2@W_att2) ----------
// R6-proven inner loop (scalar LDS fragments, 16x128 warp tile) + cp.async
// 2-stage double buffer: prefetch chunk c+1 (LDGSTS) while MMAs run chunk c.
static constexpr int GSTRIDE = 40;

__global__ __launch_bounds__(256) void k_gemm_mma(
    const float4* __restrict__ pts, const float* __restrict__ Watt2,
    const int* __restrict__ pvs) {
    __shared__ __align__(16) __half sA[2][128 * GSTRIDE];
    __shared__ __align__(16) __half sB[2][128 * GSTRIDE];
    __shared__ float sWs[1024];
    __shared__ int   svox[3][128];

    int tid = threadIdx.x;
    int warp = tid >> 5, lane = tid & 31;
    int p0 = blockIdx.x * 128;
    for (int j = tid; j < 1024; j += 256) sWs[j] = Watt2[j];
    for (int j = tid; j < 384; j += 256) {
        int i = j >> 7, r = j & 127;
        int p = p0 + r;
        svox[i][r] = (p < NPTS) ? pvs[i * NPTS + p] : 0;
    }
    __syncthreads();   // svox used by prefetch below
    const int voff[3] = {kOFF0, kOFF1, kOFF2};

    float acc[16][4];
#pragma unroll
    for (int nt = 0; nt < 16; nt++)
#pragma unroll
        for (int j = 0; j < 4; j++) acc[nt][j] = 0.f;

    // per-thread load mapping: 2 iterations x (row = idx>>2, seg = idx&3)
    int row0 = tid >> 2, row1 = (256 + tid) >> 2;
    int seg = tid & 3;
    uint32_t sa_base = smem_u32(sA), sb_base = smem_u32(sB);
    const int BUFB = 128 * GSTRIDE * 2;   // bytes per buffer stage

    auto issue_chunk = [&](int c, int buf) {
        int i_s = c >> 2, sub = c & 3;
#pragma unroll
        for (int it = 0; it < 2; it++) {
            int row = it ? row1 : row0;
            uint32_t sa = sa_base + buf * BUFB + (uint32_t)(row * GSTRIDE + seg * 8) * 2;
            const void* gsrc;
            int bytes = 16;
            int gp = p0 + row;
            if (sub < 2) {
                gsrc = &g_sf1[(size_t)gp * 192 + i_s * 64 + sub * 32 + seg * 8];
                if (gp >= NPTS) { gsrc = &g_sf1[0]; bytes = 0; }
            } else {
                int vox = svox[i_s][row];
                gsrc = &g_vmax[((size_t)(voff[i_s] + vox)) * 64 + (sub - 2) * 32 + seg * 8];
            }
            cp_async16(sa, gsrc, bytes);
            uint32_t sb = sb_base + buf * BUFB + (uint32_t)(row * GSTRIDE + seg * 8) * 2;
            cp_async16(sb, &g_wt[row * 384 + c * 32 + seg * 8], 16);
        }
        CP_COMMIT();
    };

    issue_chunk(0, 0);
    for (int c = 0; c < 12; c++) {
        int buf = c & 1;
        if (c < 11) issue_chunk(c + 1, buf ^ 1);
        if (c < 11) { CP_WAIT(1); } else { CP_WAIT(0); }
        __syncthreads();
        const __half* cA = sA[buf];
        const __half* cB = sB[buf];
#pragma unroll
        for (int ks = 0; ks < 2; ks++) {
            int ar = warp * 16 + (lane >> 2);
            int ac = ks * 16 + 2 * (lane & 3);
            uint32_t a0 = *(const uint32_t*)&cA[ar * GSTRIDE + ac];
            uint32_t a1 = *(const uint32_t*)&cA[(ar + 8) * GSTRIDE + ac];
            uint32_t a2 = *(const uint32_t*)&cA[ar * GSTRIDE + ac + 8];
            uint32_t a3 = *(const uint32_t*)&cA[(ar + 8) * GSTRIDE + ac + 8];
#pragma unroll
            for (int nt = 0; nt < 16; nt++) {
                int br = nt * 8 + (lane >> 2);
                int bc = ks * 16 + 2 * (lane & 3);
                uint32_t b0 = *(const uint32_t*)&cB[br * GSTRIDE + bc];
                uint32_t b1 = *(const uint32_t*)&cB[br * GSTRIDE + bc + 8];
                mma16816(acc[nt], a0, a1, a2, a3, b0, b1);
            }
        }
        __syncthreads();
    }

    // Epilogue: attention-2 + relu + half2 sf2 write
    int ra = p0 + warp * 16 + (lane >> 2);
    int rb = ra + 8;
#pragma unroll
    for (int rsel = 0; rsel < 2; rsel++) {
        int p = rsel ? rb : ra;
        if (p >= NPTS) continue;
        int b = kOFF3 + pvs[3 * NPTS + p];
        float inv = 1.0f / fmaxf(g_counts[b], 1.0f);
        float4 s = g_sums[b];
        float4 q = pts[p];
        float m0 = s.x * inv, m1 = s.y * inv, m2 = s.z * inv, m3 = s.w * inv;
        float a0 = q.x - m0, a1 = q.y - m1, a2 = q.z - m2, a3 = q.w;
#pragma unroll
        for (int nt = 0; nt < 16; nt++) {
            int c = nt * 8 + 2 * (lane & 3);
            float af0 = a0 * sWs[c] + a1 * sWs[128 + c] + a2 * sWs[256 + c]
                      + a3 * sWs[384 + c] + m0 * sWs[512 + c] + m1 * sWs[640 + c]
                      + m2 * sWs[768 + c] + m3 * sWs[896 + c];
            int c1 = c + 1;
            float af1 = a0 * sWs[c1] + a1 * sWs[128 + c1] + a2 * sWs[256 + c1]
                      + a3 * sWs[384 + c1] + m0 * sWs[512 + c1] + m1 * sWs[640 + c1]
                      + m2 * sWs[768 + c1] + m3 * sWs[896 + c1];
            float v0 = relu(acc[nt][rsel * 2 + 0]) * relu(af0);
            float v1 = relu(acc[nt][rsel * 2 + 1]) * relu(af1);
            *(__half2*)&g_sf2h[(size_t)p * 128 + c] = __floats2half2_rn(v0, v1);
        }
    }
}

// ------ K7: segment-max over sf2 (scale 3) -> g_omax (coalesced write) ------
__global__ __launch_bounds__(256) void k_vmax3() {
    int w = blockIdx.x * 8 + (threadIdx.x >> 5);
    if (w >= kV3) return;
    int lane = threadIdx.x & 31;
    int b = kOFF3 + w;
    int o = g_offsets[b];
    int cnt = (int)g_counts[b];
    const int* pl = &g_plist[3 * NPTS + o];
    float m0 = 0.f, m1 = 0.f, m2 = 0.f, m3 = 0.f;
    for (int t = 0; t < cnt; t++) {
        int pt = pl[t];
        size_t sb = (size_t)pt * 128 + lane;
        m0 = fmaxf(m0, __half2float(g_sf2h[sb]));
        m1 = fmaxf(m1, __half2float(g_sf2h[sb + 32]));
        m2 = fmaxf(m2, __half2float(g_sf2h[sb + 64]));
        m3 = fmaxf(m3, __half2float(g_sf2h[sb + 96]));
    }
    size_t ob = (size_t)w * 128;
    g_omax[ob + lane]      = m0;
    g_omax[ob + lane + 32] = m1;
    g_omax[ob + lane + 64] = m2;
    g_omax[ob + lane + 96] = m3;
}

// ------ K8: dense output writer, one (b,y) row per block --------------------
static constexpr int DCAP = 200;
static constexpr int DSM_BYTES = 512 * 4 + DCAP * 4 + 16 + DCAP * 129 * 4;

__global__ __launch_bounds__(256) void k_dense(float* __restrict__ out) {
    extern __shared__ char dsm[];
    int*   s_sidx = (int*)dsm;                       // [512]
    int*   s_vox  = (int*)(dsm + 2048);              // [DCAP]
    int*   s_cnt  = (int*)(dsm + 2048 + DCAP * 4);   // [1]
    float* s_om   = (float*)(dsm + 2048 + DCAP * 4 + 16); // [DCAP*129]

    int row = blockIdx.x;            // 0..kB*kH-1
    int b = row >> 9, y = row & 511;
    int tid = threadIdx.x;
    if (tid == 0) *s_cnt = 0;
    __syncthreads();

    int cellbase = b * kHW + y * kW;
    for (int x = tid; x < 512; x += 256) {
        int v = g_occmap[cellbase + x];
        int code = -1;
        if (v >= 0) {
            int slot = atomicAdd(s_cnt, 1);
            if (slot < DCAP) { s_vox[slot] = v; code = slot; }
            else             { code = -2 - v; }   // overflow: direct gather
        }
        s_sidx[x] = code;
    }
    __syncthreads();
    int cnt = min(*s_cnt, DCAP);
    for (int j = tid; j < cnt * 128; j += 256) {
        int slot = j >> 7, c = j & 127;
        s_om[slot * 129 + c] = g_omax[(size_t)s_vox[slot] * 128 + c];
    }
    __syncthreads();

    size_t outbase = ((size_t)b * 128) * kHW + (size_t)y * kW;
#pragma unroll 4
    for (int c = 0; c < 128; c++) {
        size_t ob = outbase + (size_t)c * kHW;
        for (int x = tid; x < 512; x += 256) {
            int code = s_sidx[x];
            float val = 0.f;
            if (code >= 0)       val = s_om[code * 129 + c];
            else if (code <= -2) val = g_omax[(size_t)(-2 - code) * 128 + c];
            out[ob + x] = val;
        }
    }
}

// ---------------------------------------------------------------------------
extern "C" void kernel_launch(void* const* d_in, const int* in_sizes, int n_in,
                              void* d_out, int out_size) {
    const float4* pts   = (const float4*)d_in[0];
    const float*  Wp1   = (const float*)d_in[1];
    const float*  Wa1   = (const float*)d_in[2];
    const float*  Wpt2  = (const float*)d_in[3];
    const float*  Watt2 = (const float*)d_in[4];
    const int*    pvs   = (const int*)d_in[5];
    const int*    vfs   = (const int*)d_in[6];
    float*        out   = (float*)d_out;

    cudaFuncSetAttribute(k_dense, cudaFuncAttributeMaxDynamicSharedMemorySize,
                         DSM_BYTES);

    k_zero<<<(kTOTV * 4 + 255) / 256, 256>>>();
    k_occzero<<<(kB * kHW + 255) / 256, 256>>>();
    k_occfill<<<(kV3 + 255) / 256, 256>>>(vfs);
    k_accum<<<(NPTS + 255) / 256, 256>>>(pts, pvs);
    k_scan<<<4, 1024>>>();
    k_fill<<<(NPTS + 255) / 256, 256>>>(pvs);
    k_prepw<<<(128 * 384 + 255) / 256, 256>>>(Wpt2);
    k_avfe1<<<(NPTS + 7) / 8, 256>>>(pts, Wp1, Wa1, pvs);
    k_max1<<<(kVIN + 7) / 8, 256>>>();
    k_gemm_mma<<<(NPTS + 127) / 128, 256>>>(pts, Watt2, pvs);
    k_vmax3<<<(kV3 + 7) / 8, 256>>>();
    k_dense<<<kB * kH, 256, DSM_BYTES>>>(out);
}

// round 11
// speedup vs baseline: 1.4784x; 1.0370x over previous
#include <cuda_runtime.h>
#include <cuda_fp16.h>
#include <cstdint>
#include <cstddef>

#define NPTS 300000

static constexpr int kV0 = 60000, kV1 = 30000, kV2 = 15000, kV3 = 120000;
static constexpr int kTOTV = kV0 + kV1 + kV2 + kV3;            // 225000
static constexpr int kOFF0 = 0, kOFF1 = 60000, kOFF2 = 90000, kOFF3 = 105000;
static constexpr int kVIN = kV0 + kV1 + kV2;                   // 105000
static constexpr int kB = 2, kH = 512, kW = 512, kHW = kH * kW;

// ---------------- scratch (static device globals; no allocation) -------------
__device__ float4 g_sums[kTOTV];            // per-voxel point sums (x,y,z,w)
__device__ float  g_counts[kTOTV];          // per-voxel counts
__device__ int    g_offsets[kTOTV];         // per-scale exclusive scan of counts
__device__ int    g_cursor[kTOTV];          // fill cursors
__device__ int    g_plist[4 * NPTS];        // CSR point lists, segmented per scale
__device__ __half g_sf1[(size_t)NPTS * 192];   // [N, 3*64] AVFE sf features (half)
__device__ __half g_vmax[(size_t)kVIN * 64];   // per-voxel max of sf, scales 0-2
__device__ __half g_sf2h[(size_t)NPTS * 128];  // [N,128] AVFEO sf (half)
__device__ __half g_wt[128 * 384];          // W_pt2 transposed to [n][k], half
__device__ float  g_omax[(size_t)kV3 * 128];   // per-voxel output max (coalesced)
__device__ int    g_occmap[kB * kHW];       // dense cell -> scale-3 voxel (-1 empty)

__device__ __forceinline__ float relu(float x) { return fmaxf(x, 0.f); }

__device__ __forceinline__ uint32_t smem_u32(const void* p) {
    uint32_t a;
    asm("{ .reg .u64 t; cvta.to.shared.u64 t, %1; cvt.u32.u64 %0, t; }"
        : "=r"(a) : "l"(p));
    return a;
}

__device__ __forceinline__ void cp_async16(uint32_t saddr, const void* gaddr,
                                           int src_bytes) {
    asm volatile("cp.async.cg.shared.global [%0], [%1], 16, %2;"
                 :: "r"(saddr), "l"(gaddr), "r"(src_bytes));
}
#define CP_COMMIT() asm volatile("cp.async.commit_group;" ::: "memory")
#define CP_WAIT(n)  asm volatile("cp.async.wait_group %0;" :: "n"(n) : "memory")

__device__ __forceinline__ void red_add_f4(float4* addr, float4 v) {
    asm volatile("red.global.add.v4.f32 [%0], {%1, %2, %3, %4};"
                 :: "l"(addr), "f"(v.x), "f"(v.y), "f"(v.z), "f"(v.w)
                 : "memory");
}

__device__ __forceinline__ void mma16816(float* c, uint32_t a0, uint32_t a1,
                                         uint32_t a2, uint32_t a3,
                                         uint32_t b0, uint32_t b1) {
    asm volatile(
        "mma.sync.aligned.m16n8k16.row.col.f32.f16.f16.f32 "
        "{%0,%1,%2,%3}, {%4,%5,%6,%7}, {%8,%9}, {%0,%1,%2,%3};"
        : "+f"(c[0]), "+f"(c[1]), "+f"(c[2]), "+f"(c[3])
        : "r"(a0), "r"(a1), "r"(a2), "r"(a3), "r"(b0), "r"(b1));
}

// ---------------- K0: zero scratch + occmap init (merged) -------------------
__global__ void k_zero() {
    int i = blockIdx.x * blockDim.x + threadIdx.x;
    if (i < kTOTV * 4) ((float*)g_sums)[i] = 0.f;
    if (i < kTOTV) { g_counts[i] = 0.f; g_cursor[i] = 0; }
    if (i < kB * kHW) g_occmap[i] = -1;
}
__global__ void k_occfill(const int* __restrict__ vfs) {
    int w = blockIdx.x * blockDim.x + threadIdx.x;
    if (w >= kV3) return;
    int vb = vfs[w * 3 + 0], vy = vfs[w * 3 + 1], vx = vfs[w * 3 + 2];
    g_occmap[vb * kHW + vy * kW + vx] = w;
}

// ---------------- K1: segment sums + counts, vector red.add -----------------
__global__ void k_accum(const float4* __restrict__ pts, const int* __restrict__ pvs) {
    int p = blockIdx.x * blockDim.x + threadIdx.x;
    if (p >= NPTS) return;
    float4 q = pts[p];
    const int off[4] = {kOFF0, kOFF1, kOFF2, kOFF3};
#pragma unroll
    for (int i = 0; i < 4; i++) {
        int b = off[i] + pvs[i * NPTS + p];
        red_add_f4(&g_sums[b], q);
        atomicAdd(&g_counts[b], 1.f);
    }
}

// ---------------- K2: per-scale exclusive scan of counts -> offsets ---------
__global__ void k_scan() {
    __shared__ int sh[1024];
    const int Vs[4]  = {kV0, kV1, kV2, kV3};
    const int off[4] = {kOFF0, kOFF1, kOFF2, kOFF3};
    int s = blockIdx.x;
    int V = Vs[s], base = off[s];
    int chunk = (V + 1023) / 1024;
    int lo = threadIdx.x * chunk;
    int hi = min(lo + chunk, V);
    int sum = 0;
    for (int v = lo; v < hi; v++) sum += (int)g_counts[base + v];
    sh[threadIdx.x] = sum;
    __syncthreads();
    if (threadIdx.x == 0) {
        int run = 0;
        for (int t = 0; t < 1024; t++) { int x = sh[t]; sh[t] = run; run += x; }
    }
    __syncthreads();
    int run = sh[threadIdx.x];
    for (int v = lo; v < hi; v++) { g_offsets[base + v] = run; run += (int)g_counts[base + v]; }
}

// ---------------- K3: fill CSR point lists ----------------------------------
__global__ void k_fill(const int* __restrict__ pvs) {
    int p = blockIdx.x * blockDim.x + threadIdx.x;
    if (p >= NPTS) return;
    const int off[4] = {kOFF0, kOFF1, kOFF2, kOFF3};
#pragma unroll
    for (int i = 0; i < 4; i++) {
        int b = off[i] + pvs[i * NPTS + p];
        int pos = atomicAdd(&g_cursor[b], 1);
        g_plist[i * NPTS + g_offsets[b] + pos] = p;
    }
}

// ---------------- K3b: transpose W_pt2 -> [n][k] half -----------------------
__global__ void k_prepw(const float* __restrict__ Wpt2) {
    int idx = blockIdx.x * blockDim.x + threadIdx.x;
    if (idx >= 128 * 384) return;
    int n = idx / 384, k = idx % 384;
    g_wt[idx] = __float2half(Wpt2[k * 128 + n]);
}

// ---------------- K4: AVFE point stage (3 scales), warp per point -----------
__global__ __launch_bounds__(256) void k_avfe1(
    const float4* __restrict__ pts, const float* __restrict__ Wp1,
    const float* __restrict__ Wa1, const int* __restrict__ pvs) {
    __shared__ float sWp[256];   // [4][64]
    __shared__ float sWa[512];   // [8][64]
    for (int j = threadIdx.x; j < 256; j += 256) sWp[j] = Wp1[j];
    for (int j = threadIdx.x; j < 512; j += 256) sWa[j] = Wa1[j];
    __syncthreads();

    int w = blockIdx.x * 8 + (threadIdx.x >> 5);
    if (w >= NPTS) return;
    int lane = threadIdx.x & 31;
    int c0 = lane, c1 = lane + 32;
    float4 q = pts[w];
    float pf0 = relu(q.x * sWp[c0] + q.y * sWp[64 + c0] + q.z * sWp[128 + c0] + q.w * sWp[192 + c0]);
    float pf1 = relu(q.x * sWp[c1] + q.y * sWp[64 + c1] + q.z * sWp[128 + c1] + q.w * sWp[192 + c1]);
    size_t fb = (size_t)w * 192;
    const int off[3] = {kOFF0, kOFF1, kOFF2};
#pragma unroll
    for (int i = 0; i < 3; i++) {
        int b = off[i] + pvs[i * NPTS + w];
        float inv = 1.0f / fmaxf(g_counts[b], 1.0f);
        float4 s = g_sums[b];
        float m0 = s.x * inv, m1 = s.y * inv, m2 = s.z * inv, m3 = s.w * inv;
        float a0 = q.x - m0, a1 = q.y - m1, a2 = q.z - m2, a3 = q.w;
        float af0 = a0 * sWa[c0] + a1 * sWa[64 + c0] + a2 * sWa[128 + c0] + a3 * sWa[192 + c0]
                  + m0 * sWa[256 + c0] + m1 * sWa[320 + c0] + m2 * sWa[384 + c0] + m3 * sWa[448 + c0];
        float af1 = a0 * sWa[c1] + a1 * sWa[64 + c1] + a2 * sWa[128 + c1] + a3 * sWa[192 + c1]
                  + m0 * sWa[256 + c1] + m1 * sWa[320 + c1] + m2 * sWa[384 + c1] + m3 * sWa[448 + c1];
        g_sf1[fb + i * 64 + c0] = __float2half(pf0 * relu(af0));
        g_sf1[fb + i * 64 + c1] = __float2half(pf1 * relu(af1));
    }
}

// ------ K5: segment-max (scales 0-2) -> g_vmax[V,64] (R6-proven body) -------
__global__ __launch_bounds__(256) void k_max1() {
    int w = blockIdx.x * 8 + (threadIdx.x >> 5);
    if (w >= kVIN) return;
    int lane = threadIdx.x & 31;
    int i;
    if (w < kV0)            i = 0;
    else if (w < kV0 + kV1) i = 1;
    else                    i = 2;
    int b = w;                       // packed global voxel index, scales 0-2
    int o = g_offsets[b];
    int cnt = (int)g_counts[b];
    const int* pl = &g_plist[i * NPTS + o];
    float m0 = 0.f, m1 = 0.f;        // sf >= 0 always (product of relus)
    for (int t = 0; t < cnt; t++) {
        int pt = pl[t];
        size_t fb = (size_t)pt * 192 + i * 64;
        m0 = fmaxf(m0, __half2float(g_sf1[fb + lane]));
        m1 = fmaxf(m1, __half2float(g_sf1[fb + lane + 32]));
    }
    g_vmax[(size_t)b * 64 + lane]      = __float2half(m0);
    g_vmax[(size_t)b * 64 + lane + 32] = __float2half(m1);
}

// ------ K6: HMMA GEMM  sf2 = relu(final@W_pt2) * relu(att2@W_att2) ----------
// R6-proven inner loop (scalar LDS fragments, 16x128 warp tile) + cp.async
// 2-stage double buffer: prefetch chunk c+1 (LDGSTS) while MMAs run chunk c.
static constexpr int GSTRIDE = 40;

__global__ __launch_bounds__(256) void k_gemm_mma(
    const float4* __restrict__ pts, const float* __restrict__ Watt2,
    const int* __restrict__ pvs) {
    __shared__ __align__(16) __half sA[2][128 * GSTRIDE];
    __shared__ __align__(16) __half sB[2][128 * GSTRIDE];
    __shared__ float sWs[1024];
    __shared__ int   svox[3][128];

    int tid = threadIdx.x;
    int warp = tid >> 5, lane = tid & 31;
    int p0 = blockIdx.x * 128;
    for (int j = tid; j < 1024; j += 256) sWs[j] = Watt2[j];
    for (int j = tid; j < 384; j += 256) {
        int i = j >> 7, r = j & 127;
        int p = p0 + r;
        svox[i][r] = (p < NPTS) ? pvs[i * NPTS + p] : 0;
    }
    __syncthreads();   // svox used by prefetch below
    const int voff[3] = {kOFF0, kOFF1, kOFF2};

    float acc[16][4];
#pragma unroll
    for (int nt = 0; nt < 16; nt++)
#pragma unroll
        for (int j = 0; j < 4; j++) acc[nt][j] = 0.f;

    // per-thread load mapping: 2 iterations x (row = idx>>2, seg = idx&3)
    int row0 = tid >> 2, row1 = (256 + tid) >> 2;
    int seg = tid & 3;
    uint32_t sa_base = smem_u32(sA), sb_base = smem_u32(sB);
    const int BUFB = 128 * GSTRIDE * 2;   // bytes per buffer stage

    auto issue_chunk = [&](int c, int buf) {
        int i_s = c >> 2, sub = c & 3;
#pragma unroll
        for (int it = 0; it < 2; it++) {
            int row = it ? row1 : row0;
            uint32_t sa = sa_base + buf * BUFB + (uint32_t)(row * GSTRIDE + seg * 8) * 2;
            const void* gsrc;
            int bytes = 16;
            int gp = p0 + row;
            if (sub < 2) {
                gsrc = &g_sf1[(size_t)gp * 192 + i_s * 64 + sub * 32 + seg * 8];
                if (gp >= NPTS) { gsrc = &g_sf1[0]; bytes = 0; }
            } else {
                int vox = svox[i_s][row];
                gsrc = &g_vmax[((size_t)(voff[i_s] + vox)) * 64 + (sub - 2) * 32 + seg * 8];
            }
            cp_async16(sa, gsrc, bytes);
            uint32_t sb = sb_base + buf * BUFB + (uint32_t)(row * GSTRIDE + seg * 8) * 2;
            cp_async16(sb, &g_wt[row * 384 + c * 32 + seg * 8], 16);
        }
        CP_COMMIT();
    };

    issue_chunk(0, 0);
    for (int c = 0; c < 12; c++) {
        int buf = c & 1;
        if (c < 11) issue_chunk(c + 1, buf ^ 1);
        if (c < 11) { CP_WAIT(1); } else { CP_WAIT(0); }
        __syncthreads();
        const __half* cA = sA[buf];
        const __half* cB = sB[buf];
#pragma unroll
        for (int ks = 0; ks < 2; ks++) {
            int ar = warp * 16 + (lane >> 2);
            int ac = ks * 16 + 2 * (lane & 3);
            uint32_t a0 = *(const uint32_t*)&cA[ar * GSTRIDE + ac];
            uint32_t a1 = *(const uint32_t*)&cA[(ar + 8) * GSTRIDE + ac];
            uint32_t a2 = *(const uint32_t*)&cA[ar * GSTRIDE + ac + 8];
            uint32_t a3 = *(const uint32_t*)&cA[(ar + 8) * GSTRIDE + ac + 8];
#pragma unroll
            for (int nt = 0; nt < 16; nt++) {
                int br = nt * 8 + (lane >> 2);
                int bc = ks * 16 + 2 * (lane & 3);
                uint32_t b0 = *(const uint32_t*)&cB[br * GSTRIDE + bc];
                uint32_t b1 = *(const uint32_t*)&cB[br * GSTRIDE + bc + 8];
                mma16816(acc[nt], a0, a1, a2, a3, b0, b1);
            }
        }
        __syncthreads();
    }

    // Epilogue: attention-2 + relu + half2 sf2 write
    int ra = p0 + warp * 16 + (lane >> 2);
    int rb = ra + 8;
#pragma unroll
    for (int rsel = 0; rsel < 2; rsel++) {
        int p = rsel ? rb : ra;
        if (p >= NPTS) continue;
        int b = kOFF3 + pvs[3 * NPTS + p];
        float inv = 1.0f / fmaxf(g_counts[b], 1.0f);
        float4 s = g_sums[b];
        float4 q = pts[p];
        float m0 = s.x * inv, m1 = s.y * inv, m2 = s.z * inv, m3 = s.w * inv;
        float a0 = q.x - m0, a1 = q.y - m1, a2 = q.z - m2, a3 = q.w;
#pragma unroll
        for (int nt = 0; nt < 16; nt++) {
            int c = nt * 8 + 2 * (lane & 3);
            float af0 = a0 * sWs[c] + a1 * sWs[128 + c] + a2 * sWs[256 + c]
                      + a3 * sWs[384 + c] + m0 * sWs[512 + c] + m1 * sWs[640 + c]
                      + m2 * sWs[768 + c] + m3 * sWs[896 + c];
            int c1 = c + 1;
            float af1 = a0 * sWs[c1] + a1 * sWs[128 + c1] + a2 * sWs[256 + c1]
                      + a3 * sWs[384 + c1] + m0 * sWs[512 + c1] + m1 * sWs[640 + c1]
                      + m2 * sWs[768 + c1] + m3 * sWs[896 + c1];
            float v0 = relu(acc[nt][rsel * 2 + 0]) * relu(af0);
            float v1 = relu(acc[nt][rsel * 2 + 1]) * relu(af1);
            *(__half2*)&g_sf2h[(size_t)p * 128 + c] = __floats2half2_rn(v0, v1);
        }
    }
}

// ------ K7: segment-max over sf2 (scale 3) -> g_omax (coalesced write) ------
__global__ __launch_bounds__(256) void k_vmax3() {
    int w = blockIdx.x * 8 + (threadIdx.x >> 5);
    if (w >= kV3) return;
    int lane = threadIdx.x & 31;
    int b = kOFF3 + w;
    int o = g_offsets[b];
    int cnt = (int)g_counts[b];
    const int* pl = &g_plist[3 * NPTS + o];
    float m0 = 0.f, m1 = 0.f, m2 = 0.f, m3 = 0.f;
    for (int t = 0; t < cnt; t++) {
        int pt = pl[t];
        size_t sb = (size_t)pt * 128 + lane;
        m0 = fmaxf(m0, __half2float(g_sf2h[sb]));
        m1 = fmaxf(m1, __half2float(g_sf2h[sb + 32]));
        m2 = fmaxf(m2, __half2float(g_sf2h[sb + 64]));
        m3 = fmaxf(m3, __half2float(g_sf2h[sb + 96]));
    }
    size_t ob = (size_t)w * 128;
    g_omax[ob + lane]      = m0;
    g_omax[ob + lane + 32] = m1;
    g_omax[ob + lane + 64] = m2;
    g_omax[ob + lane + 96] = m3;
}

// ------ K8: dense output writer, one (b,y) row per block --------------------
static constexpr int DCAP = 200;
static constexpr int DSM_BYTES = 512 * 4 + DCAP * 4 + 16 + DCAP * 129 * 4;

__global__ __launch_bounds__(256) void k_dense(float* __restrict__ out) {
    extern __shared__ char dsm[];
    int*   s_sidx = (int*)dsm;                       // [512]
    int*   s_vox  = (int*)(dsm + 2048);              // [DCAP]
    int*   s_cnt  = (int*)(dsm + 2048 + DCAP * 4);   // [1]
    float* s_om   = (float*)(dsm + 2048 + DCAP * 4 + 16); // [DCAP*129]

    int row = blockIdx.x;            // 0..kB*kH-1
    int b = row >> 9, y = row & 511;
    int tid = threadIdx.x;
    if (tid == 0) *s_cnt = 0;
    __syncthreads();

    int cellbase = b * kHW + y * kW;
    for (int x = tid; x < 512; x += 256) {
        int v = g_occmap[cellbase + x];
        int code = -1;
        if (v >= 0) {
            int slot = atomicAdd(s_cnt, 1);
            if (slot < DCAP) { s_vox[slot] = v; code = slot; }
            else             { code = -2 - v; }   // overflow: direct gather
        }
        s_sidx[x] = code;
    }
    __syncthreads();
    int cnt = min(*s_cnt, DCAP);
    for (int j = tid; j < cnt * 128; j += 256) {
        int slot = j >> 7, c = j & 127;
        s_om[slot * 129 + c] = g_omax[(size_t)s_vox[slot] * 128 + c];
    }
    __syncthreads();

    size_t outbase = ((size_t)b * 128) * kHW + (size_t)y * kW;
#pragma unroll 4
    for (int c = 0; c < 128; c++) {
        size_t ob = outbase + (size_t)c * kHW;
        for (int x = tid; x < 512; x += 256) {
            int code = s_sidx[x];
            float val = 0.f;
            if (code >= 0)       val = s_om[code * 129 + c];
            else if (code <= -2) val = g_omax[(size_t)(-2 - code) * 128 + c];
            out[ob + x] = val;
        }
    }
}

// ---------------------------------------------------------------------------
extern "C" void kernel_launch(void* const* d_in, const int* in_sizes, int n_in,
                              void* d_out, int out_size) {
    const float4* pts   = (const float4*)d_in[0];
    const float*  Wp1   = (const float*)d_in[1];
    const float*  Wa1   = (const float*)d_in[2];
    const float*  Wpt2  = (const float*)d_in[3];
    const float*  Watt2 = (const float*)d_in[4];
    const int*    pvs   = (const int*)d_in[5];
    const int*    vfs   = (const int*)d_in[6];
    float*        out   = (float*)d_out;

    cudaFuncSetAttribute(k_dense, cudaFuncAttributeMaxDynamicSharedMemorySize,
                         DSM_BYTES);

    k_zero<<<(kTOTV * 4 + 255) / 256, 256>>>();
    k_occfill<<<(kV3 + 255) / 256, 256>>>(vfs);
    k_accum<<<(NPTS + 255) / 256, 256>>>(pts, pvs);
    k_scan<<<4, 1024>>>();
    k_fill<<<(NPTS + 255) / 256, 256>>>(pvs);
    k_prepw<<<(128 * 384 + 255) / 256, 256>>>(Wpt2);
    k_avfe1<<<(NPTS + 7) / 8, 256>>>(pts, Wp1, Wa1, pvs);
    k_max1<<<(kVIN + 7) / 8, 256>>>();
    k_gemm_mma<<<(NPTS + 127) / 128, 256>>>(pts, Watt2, pvs);
    k_vmax3<<<(kV3 + 7) / 8, 256>>>();
    k_dense<<<kB * kH, 256, DSM_BYTES>>>(out);
}

// round 12
// speedup vs baseline: 1.7397x; 1.1768x over previous
#include <cuda_runtime.h>
#include <cuda_fp16.h>
#include <cstdint>
#include <cstddef>

#define NPTS 300000

static constexpr int kV0 = 60000, kV1 = 30000, kV2 = 15000, kV3 = 120000;
static constexpr int kTOTV = kV0 + kV1 + kV2 + kV3;            // 225000
static constexpr int kOFF0 = 0, kOFF1 = 60000, kOFF2 = 90000, kOFF3 = 105000;
static constexpr int kVIN = kV0 + kV1 + kV2;                   // 105000
static constexpr int kB = 2, kH = 512, kW = 512, kHW = kH * kW;
static constexpr int kSCB = (kTOTV + 1023) / 1024;             // 220 scan blocks

// ---------------- scratch (static device globals; no allocation) -------------
__device__ float4 g_sums[kTOTV];            // per-voxel point sums (x,y,z,w)
__device__ float  g_counts[kTOTV];          // per-voxel counts
__device__ int    g_offsets[kTOTV];         // per-scale exclusive scan of counts
__device__ int    g_cursor[kTOTV];          // fill cursors
__device__ int    g_blk[256];               // scan block totals
__device__ int    g_plist[4 * NPTS];        // CSR point lists, segmented per scale
__device__ __half g_sf1[(size_t)NPTS * 192];   // [N, 3*64] AVFE sf features (half)
__device__ __half g_vmax[(size_t)kVIN * 64];   // per-voxel max of sf, scales 0-2
__device__ __half g_sf2h[(size_t)NPTS * 128];  // [N,128] AVFEO sf (half)
__device__ __half g_wt[128 * 384];          // W_pt2 transposed to [n][k], half
__device__ float  g_omax[(size_t)kV3 * 128];   // per-voxel output max (coalesced)
__device__ int    g_occmap[kB * kHW];       // dense cell -> scale-3 voxel (-1 empty)

__device__ __forceinline__ float relu(float x) { return fmaxf(x, 0.f); }

__device__ __forceinline__ uint32_t smem_u32(const void* p) {
    uint32_t a;
    asm("{ .reg .u64 t; cvta.to.shared.u64 t, %1; cvt.u32.u64 %0, t; }"
        : "=r"(a) : "l"(p));
    return a;
}

__device__ __forceinline__ void cp_async16(uint32_t saddr, const void* gaddr,
                                           int src_bytes) {
    asm volatile("cp.async.cg.shared.global [%0], [%1], 16, %2;"
                 :: "r"(saddr), "l"(gaddr), "r"(src_bytes));
}
#define CP_COMMIT() asm volatile("cp.async.commit_group;" ::: "memory")
#define CP_WAIT(n)  asm volatile("cp.async.wait_group %0;" :: "n"(n) : "memory")

__device__ __forceinline__ void red_add_f4(float4* addr, float4 v) {
    asm volatile("red.global.add.v4.f32 [%0], {%1, %2, %3, %4};"
                 :: "l"(addr), "f"(v.x), "f"(v.y), "f"(v.z), "f"(v.w)
                 : "memory");
}

__device__ __forceinline__ void mma16816(float* c, uint32_t a0, uint32_t a1,
                                         uint32_t a2, uint32_t a3,
                                         uint32_t b0, uint32_t b1) {
    asm volatile(
        "mma.sync.aligned.m16n8k16.row.col.f32.f16.f16.f32 "
        "{%0,%1,%2,%3}, {%4,%5,%6,%7}, {%8,%9}, {%0,%1,%2,%3};"
        : "+f"(c[0]), "+f"(c[1]), "+f"(c[2]), "+f"(c[3])
        : "r"(a0), "r"(a1), "r"(a2), "r"(a3), "r"(b0), "r"(b1));
}

// ---------------- K0: zero scratch + occmap init (merged) -------------------
__global__ void k_zero() {
    int i = blockIdx.x * blockDim.x + threadIdx.x;
    if (i < kTOTV * 4) ((float*)g_sums)[i] = 0.f;
    if (i < kTOTV) { g_counts[i] = 0.f; g_cursor[i] = 0; }
    if (i < kB * kHW) g_occmap[i] = -1;
}
__global__ void k_occfill(const int* __restrict__ vfs) {
    int w = blockIdx.x * blockDim.x + threadIdx.x;
    if (w >= kV3) return;
    int vb = vfs[w * 3 + 0], vy = vfs[w * 3 + 1], vx = vfs[w * 3 + 2];
    g_occmap[vb * kHW + vy * kW + vx] = w;
}

// ---------------- K1: segment sums + counts, vector red.add -----------------
__global__ void k_accum(const float4* __restrict__ pts, const int* __restrict__ pvs) {
    int p = blockIdx.x * blockDim.x + threadIdx.x;
    if (p >= NPTS) return;
    float4 q = pts[p];
    const int off[4] = {kOFF0, kOFF1, kOFF2, kOFF3};
#pragma unroll
    for (int i = 0; i < 4; i++) {
        int b = off[i] + pvs[i * NPTS + p];
        red_add_f4(&g_sums[b], q);
        atomicAdd(&g_counts[b], 1.f);
    }
}

// ---------------- K2: global 3-phase exclusive scan of counts ---------------
// Per-scale offsets via the identity gscan[scale_base] == scale_idx * NPTS
// (each point appears exactly once per scale), so segmented scan ==
// global scan - i*NPTS.
__global__ __launch_bounds__(256) void k_scanA() {
    __shared__ int s[1024];
    __shared__ int warpsum[8];
    int b = blockIdx.x, tid = threadIdx.x;
    int base = b * 1024;
    for (int k = tid; k < 1024; k += 256) {
        int j = base + k;
        s[k] = (j < kTOTV) ? (int)g_counts[j] : 0;
    }
    __syncthreads();
    int e0 = s[4 * tid], e1 = s[4 * tid + 1], e2 = s[4 * tid + 2], e3 = s[4 * tid + 3];
    int tsum = e0 + e1 + e2 + e3;
    int lane = tid & 31, wid = tid >> 5;
    int x = tsum;
#pragma unroll
    for (int o = 1; o < 32; o <<= 1) {
        int y = __shfl_up_sync(~0u, x, o);
        if (lane >= o) x += y;
    }
    if (lane == 31) warpsum[wid] = x;
    __syncthreads();
    if (wid == 0) {
        int w = (lane < 8) ? warpsum[lane] : 0;
#pragma unroll
        for (int o = 1; o < 8; o <<= 1) {
            int y = __shfl_up_sync(~0u, w, o);
            if (lane >= o) w += y;
        }
        if (lane < 8) warpsum[lane] = w;   // inclusive warp totals
    }
    __syncthreads();
    int warpoff = (wid > 0) ? warpsum[wid - 1] : 0;
    int texcl = warpoff + x - tsum;        // exclusive prefix for this thread
    int j = base + 4 * tid;
    if (j < kTOTV)     g_offsets[j]     = texcl;
    texcl += e0;
    if (j + 1 < kTOTV) g_offsets[j + 1] = texcl;
    texcl += e1;
    if (j + 2 < kTOTV) g_offsets[j + 2] = texcl;
    texcl += e2;
    if (j + 3 < kTOTV) g_offsets[j + 3] = texcl;
    if (tid == 0) g_blk[b] = warpsum[7];
}

__global__ void k_scanB() {   // 1 block, 32 threads: exclusive scan of g_blk
    __shared__ int s[224];
    int tid = threadIdx.x;
    for (int k = tid; k < kSCB; k += 32) s[k] = g_blk[k];
    __syncwarp();
    int loc[7]; int sum = 0;
#pragma unroll
    for (int u = 0; u < 7; u++) {
        int k = tid * 7 + u;
        int v = (k < kSCB) ? s[k] : 0;
        loc[u] = sum; sum += v;
    }
    int x = sum;
#pragma unroll
    for (int o = 1; o < 32; o <<= 1) {
        int y = __shfl_up_sync(~0u, x, o);
        if (tid >= o) x += y;
    }
    int excl = x - sum;
#pragma unroll
    for (int u = 0; u < 7; u++) {
        int k = tid * 7 + u;
        if (k < kSCB) g_blk[k] = excl + loc[u];
    }
}

__global__ void k_scanC() {
    int j = blockIdx.x * 256 + threadIdx.x;
    if (j >= kTOTV) return;
    int sb;
    if (j < kOFF1)      sb = 0;
    else if (j < kOFF2) sb = NPTS;
    else if (j < kOFF3) sb = 2 * NPTS;
    else                sb = 3 * NPTS;
    g_offsets[j] += g_blk[j >> 10] - sb;
}

// ---------------- K3: fill CSR point lists ----------------------------------
__global__ void k_fill(const int* __restrict__ pvs) {
    int p = blockIdx.x * blockDim.x + threadIdx.x;
    if (p >= NPTS) return;
    const int off[4] = {kOFF0, kOFF1, kOFF2, kOFF3};
#pragma unroll
    for (int i = 0; i < 4; i++) {
        int b = off[i] + pvs[i * NPTS + p];
        int pos = atomicAdd(&g_cursor[b], 1);
        g_plist[i * NPTS + g_offsets[b] + pos] = p;
    }
}

// ---------------- K3b: transpose W_pt2 -> [n][k] half -----------------------
__global__ void k_prepw(const float* __restrict__ Wpt2) {
    int idx = blockIdx.x * blockDim.x + threadIdx.x;
    if (idx >= 128 * 384) return;
    int n = idx / 384, k = idx % 384;
    g_wt[idx] = __float2half(Wpt2[k * 128 + n]);
}

// ---------------- K4: AVFE point stage (3 scales), warp per point -----------
__global__ __launch_bounds__(256) void k_avfe1(
    const float4* __restrict__ pts, const float* __restrict__ Wp1,
    const float* __restrict__ Wa1, const int* __restrict__ pvs) {
    __shared__ float sWp[256];   // [4][64]
    __shared__ float sWa[512];   // [8][64]
    for (int j = threadIdx.x; j < 256; j += 256) sWp[j] = Wp1[j];
    for (int j = threadIdx.x; j < 512; j += 256) sWa[j] = Wa1[j];
    __syncthreads();

    int w = blockIdx.x * 8 + (threadIdx.x >> 5);
    if (w >= NPTS) return;
    int lane = threadIdx.x & 31;
    int c0 = lane, c1 = lane + 32;
    float4 q = pts[w];
    float pf0 = relu(q.x * sWp[c0] + q.y * sWp[64 + c0] + q.z * sWp[128 + c0] + q.w * sWp[192 + c0]);
    float pf1 = relu(q.x * sWp[c1] + q.y * sWp[64 + c1] + q.z * sWp[128 + c1] + q.w * sWp[192 + c1]);
    size_t fb = (size_t)w * 192;
    const int off[3] = {kOFF0, kOFF1, kOFF2};
#pragma unroll
    for (int i = 0; i < 3; i++) {
        int b = off[i] + pvs[i * NPTS + w];
        float inv = 1.0f / fmaxf(g_counts[b], 1.0f);
        float4 s = g_sums[b];
        float m0 = s.x * inv, m1 = s.y * inv, m2 = s.z * inv, m3 = s.w * inv;
        float a0 = q.x - m0, a1 = q.y - m1, a2 = q.z - m2, a3 = q.w;
        float af0 = a0 * sWa[c0] + a1 * sWa[64 + c0] + a2 * sWa[128 + c0] + a3 * sWa[192 + c0]
                  + m0 * sWa[256 + c0] + m1 * sWa[320 + c0] + m2 * sWa[384 + c0] + m3 * sWa[448 + c0];
        float af1 = a0 * sWa[c1] + a1 * sWa[64 + c1] + a2 * sWa[128 + c1] + a3 * sWa[192 + c1]
                  + m0 * sWa[256 + c1] + m1 * sWa[320 + c1] + m2 * sWa[384 + c1] + m3 * sWa[448 + c1];
        g_sf1[fb + i * 64 + c0] = __float2half(pf0 * relu(af0));
        g_sf1[fb + i * 64 + c1] = __float2half(pf1 * relu(af1));
    }
}

// ------ K5: segment-max (scales 0-2) -> g_vmax[V,64] (R6-proven body) -------
__global__ __launch_bounds__(256) void k_max1() {
    int w = blockIdx.x * 8 + (threadIdx.x >> 5);
    if (w >= kVIN) return;
    int lane = threadIdx.x & 31;
    int i;
    if (w < kV0)            i = 0;
    else if (w < kV0 + kV1) i = 1;
    else                    i = 2;
    int b = w;                       // packed global voxel index, scales 0-2
    int o = g_offsets[b];
    int cnt = (int)g_counts[b];
    const int* pl = &g_plist[i * NPTS + o];
    float m0 = 0.f, m1 = 0.f;        // sf >= 0 always (product of relus)
    for (int t = 0; t < cnt; t++) {
        int pt = pl[t];
        size_t fb = (size_t)pt * 192 + i * 64;
        m0 = fmaxf(m0, __half2float(g_sf1[fb + lane]));
        m1 = fmaxf(m1, __half2float(g_sf1[fb + lane + 32]));
    }
    g_vmax[(size_t)b * 64 + lane]      = __float2half(m0);
    g_vmax[(size_t)b * 64 + lane + 32] = __float2half(m1);
}

// ------ K6: HMMA GEMM  sf2 = relu(final@W_pt2) * relu(att2@W_att2) ----------
// R6-proven inner loop (scalar LDS fragments, 16x128 warp tile) + cp.async
// 2-stage double buffer: prefetch chunk c+1 (LDGSTS) while MMAs run chunk c.
static constexpr int GSTRIDE = 40;

__global__ __launch_bounds__(256) void k_gemm_mma(
    const float4* __restrict__ pts, const float* __restrict__ Watt2,
    const int* __restrict__ pvs) {
    __shared__ __align__(16) __half sA[2][128 * GSTRIDE];
    __shared__ __align__(16) __half sB[2][128 * GSTRIDE];
    __shared__ float sWs[1024];
    __shared__ int   svox[3][128];

    int tid = threadIdx.x;
    int warp = tid >> 5, lane = tid & 31;
    int p0 = blockIdx.x * 128;
    for (int j = tid; j < 1024; j += 256) sWs[j] = Watt2[j];
    for (int j = tid; j < 384; j += 256) {
        int i = j >> 7, r = j & 127;
        int p = p0 + r;
        svox[i][r] = (p < NPTS) ? pvs[i * NPTS + p] : 0;
    }
    __syncthreads();   // svox used by prefetch below
    const int voff[3] = {kOFF0, kOFF1, kOFF2};

    float acc[16][4];
#pragma unroll
    for (int nt = 0; nt < 16; nt++)
#pragma unroll
        for (int j = 0; j < 4; j++) acc[nt][j] = 0.f;

    int row0 = tid >> 2, row1 = (256 + tid) >> 2;
    int seg = tid & 3;
    uint32_t sa_base = smem_u32(sA), sb_base = smem_u32(sB);
    const int BUFB = 128 * GSTRIDE * 2;   // bytes per buffer stage

    auto issue_chunk = [&](int c, int buf) {
        int i_s = c >> 2, sub = c & 3;
#pragma unroll
        for (int it = 0; it < 2; it++) {
            int row = it ? row1 : row0;
            uint32_t sa = sa_base + buf * BUFB + (uint32_t)(row * GSTRIDE + seg * 8) * 2;
            const void* gsrc;
            int bytes = 16;
            int gp = p0 + row;
            if (sub < 2) {
                gsrc = &g_sf1[(size_t)gp * 192 + i_s * 64 + sub * 32 + seg * 8];
                if (gp >= NPTS) { gsrc = &g_sf1[0]; bytes = 0; }
            } else {
                int vox = svox[i_s][row];
                gsrc = &g_vmax[((size_t)(voff[i_s] + vox)) * 64 + (sub - 2) * 32 + seg * 8];
            }
            cp_async16(sa, gsrc, bytes);
            uint32_t sb = sb_base + buf * BUFB + (uint32_t)(row * GSTRIDE + seg * 8) * 2;
            cp_async16(sb, &g_wt[row * 384 + c * 32 + seg * 8], 16);
        }
        CP_COMMIT();
    };

    issue_chunk(0, 0);
    for (int c = 0; c < 12; c++) {
        int buf = c & 1;
        if (c < 11) issue_chunk(c + 1, buf ^ 1);
        if (c < 11) { CP_WAIT(1); } else { CP_WAIT(0); }
        __syncthreads();
        const __half* cA = sA[buf];
        const __half* cB = sB[buf];
#pragma unroll
        for (int ks = 0; ks < 2; ks++) {
            int ar = warp * 16 + (lane >> 2);
            int ac = ks * 16 + 2 * (lane & 3);
            uint32_t a0 = *(const uint32_t*)&cA[ar * GSTRIDE + ac];
            uint32_t a1 = *(const uint32_t*)&cA[(ar + 8) * GSTRIDE + ac];
            uint32_t a2 = *(const uint32_t*)&cA[ar * GSTRIDE + ac + 8];
            uint32_t a3 = *(const uint32_t*)&cA[(ar + 8) * GSTRIDE + ac + 8];
#pragma unroll
            for (int nt = 0; nt < 16; nt++) {
                int br = nt * 8 + (lane >> 2);
                int bc = ks * 16 + 2 * (lane & 3);
                uint32_t b0 = *(const uint32_t*)&cB[br * GSTRIDE + bc];
                uint32_t b1 = *(const uint32_t*)&cB[br * GSTRIDE + bc + 8];
                mma16816(acc[nt], a0, a1, a2, a3, b0, b1);
            }
        }
        __syncthreads();
    }

    // Epilogue: attention-2 + relu + half2 sf2 write
    int ra = p0 + warp * 16 + (lane >> 2);
    int rb = ra + 8;
#pragma unroll
    for (int rsel = 0; rsel < 2; rsel++) {
        int p = rsel ? rb : ra;
        if (p >= NPTS) continue;
        int b = kOFF3 + pvs[3 * NPTS + p];
        float inv = 1.0f / fmaxf(g_counts[b], 1.0f);
        float4 s = g_sums[b];
        float4 q = pts[p];
        float m0 = s.x * inv, m1 = s.y * inv, m2 = s.z * inv, m3 = s.w * inv;
        float a0 = q.x - m0, a1 = q.y - m1, a2 = q.z - m2, a3 = q.w;
#pragma unroll
        for (int nt = 0; nt < 16; nt++) {
            int c = nt * 8 + 2 * (lane & 3);
            float af0 = a0 * sWs[c] + a1 * sWs[128 + c] + a2 * sWs[256 + c]
                      + a3 * sWs[384 + c] + m0 * sWs[512 + c] + m1 * sWs[640 + c]
                      + m2 * sWs[768 + c] + m3 * sWs[896 + c];
            int c1 = c + 1;
            float af1 = a0 * sWs[c1] + a1 * sWs[128 + c1] + a2 * sWs[256 + c1]
                      + a3 * sWs[384 + c1] + m0 * sWs[512 + c1] + m1 * sWs[640 + c1]
                      + m2 * sWs[768 + c1] + m3 * sWs[896 + c1];
            float v0 = relu(acc[nt][rsel * 2 + 0]) * relu(af0);
            float v1 = relu(acc[nt][rsel * 2 + 1]) * relu(af1);
            *(__half2*)&g_sf2h[(size_t)p * 128 + c] = __floats2half2_rn(v0, v1);
        }
    }
}

// ------ K7: segment-max over sf2 (scale 3) -> g_omax (coalesced write) ------
__global__ __launch_bounds__(256) void k_vmax3() {
    int w = blockIdx.x * 8 + (threadIdx.x >> 5);
    if (w >= kV3) return;
    int lane = threadIdx.x & 31;
    int b = kOFF3 + w;
    int o = g_offsets[b];
    int cnt = (int)g_counts[b];
    const int* pl = &g_plist[3 * NPTS + o];
    float m0 = 0.f, m1 = 0.f, m2 = 0.f, m3 = 0.f;
    for (int t = 0; t < cnt; t++) {
        int pt = pl[t];
        size_t sb = (size_t)pt * 128 + lane;
        m0 = fmaxf(m0, __half2float(g_sf2h[sb]));
        m1 = fmaxf(m1, __half2float(g_sf2h[sb + 32]));
        m2 = fmaxf(m2, __half2float(g_sf2h[sb + 64]));
        m3 = fmaxf(m3, __half2float(g_sf2h[sb + 96]));
    }
    size_t ob = (size_t)w * 128;
    g_omax[ob + lane]      = m0;
    g_omax[ob + lane + 32] = m1;
    g_omax[ob + lane + 64] = m2;
    g_omax[ob + lane + 96] = m3;
}

// ------ K8: dense output writer, one (b,y) row per block --------------------
static constexpr int DCAP = 200;
static constexpr int DSM_BYTES = 512 * 4 + DCAP * 4 + 16 + DCAP * 129 * 4;

__global__ __launch_bounds__(256) void k_dense(float* __restrict__ out) {
    extern __shared__ char dsm[];
    int*   s_sidx = (int*)dsm;                       // [512]
    int*   s_vox  = (int*)(dsm + 2048);              // [DCAP]
    int*   s_cnt  = (int*)(dsm + 2048 + DCAP * 4);   // [1]
    float* s_om   = (float*)(dsm + 2048 + DCAP * 4 + 16); // [DCAP*129]

    int row = blockIdx.x;            // 0..kB*kH-1
    int b = row >> 9, y = row & 511;
    int tid = threadIdx.x;
    if (tid == 0) *s_cnt = 0;
    __syncthreads();

    int cellbase = b * kHW + y * kW;
    for (int x = tid; x < 512; x += 256) {
        int v = g_occmap[cellbase + x];
        int code = -1;
        if (v >= 0) {
            int slot = atomicAdd(s_cnt, 1);
            if (slot < DCAP) { s_vox[slot] = v; code = slot; }
            else             { code = -2 - v; }   // overflow: direct gather
        }
        s_sidx[x] = code;
    }
    __syncthreads();
    int cnt = min(*s_cnt, DCAP);
    for (int j = tid; j < cnt * 128; j += 256) {
        int slot = j >> 7, c = j & 127;
        s_om[slot * 129 + c] = g_omax[(size_t)s_vox[slot] * 128 + c];
    }
    __syncthreads();

    size_t outbase = ((size_t)b * 128) * kHW + (size_t)y * kW;
#pragma unroll 4
    for (int c = 0; c < 128; c++) {
        size_t ob = outbase + (size_t)c * kHW;
        for (int x = tid; x < 512; x += 256) {
            int code = s_sidx[x];
            float val = 0.f;
            if (code >= 0)       val = s_om[code * 129 + c];
            else if (code <= -2) val = g_omax[(size_t)(-2 - code) * 128 + c];
            out[ob + x] = val;
        }
    }
}

// ---------------------------------------------------------------------------
extern "C" void kernel_launch(void* const* d_in, const int* in_sizes, int n_in,
                              void* d_out, int out_size) {
    const float4* pts   = (const float4*)d_in[0];
    const float*  Wp1   = (const float*)d_in[1];
    const float*  Wa1   = (const float*)d_in[2];
    const float*  Wpt2  = (const float*)d_in[3];
    const float*  Watt2 = (const float*)d_in[4];
    const int*    pvs   = (const int*)d_in[5];
    const int*    vfs   = (const int*)d_in[6];
    float*        out   = (float*)d_out;

    cudaFuncSetAttribute(k_dense, cudaFuncAttributeMaxDynamicSharedMemorySize,
                         DSM_BYTES);

    k_zero<<<(kTOTV * 4 + 255) / 256, 256>>>();
    k_occfill<<<(kV3 + 255) / 256, 256>>>(vfs);
    k_accum<<<(NPTS + 255) / 256, 256>>>(pts, pvs);
    k_scanA<<<kSCB, 256>>>();
    k_scanB<<<1, 32>>>();
    k_scanC<<<(kTOTV + 255) / 256, 256>>>();
    k_fill<<<(NPTS + 255) / 256, 256>>>(pvs);
    k_prepw<<<(128 * 384 + 255) / 256, 256>>>(Wpt2);
    k_avfe1<<<(NPTS + 7) / 8, 256>>>(pts, Wp1, Wa1, pvs);
    k_max1<<<(kVIN + 7) / 8, 256>>>();
    k_gemm_mma<<<(NPTS + 127) / 128, 256>>>(pts, Watt2, pvs);
    k_vmax3<<<(kV3 + 7) / 8, 256>>>();
    k_dense<<<kB * kH, 256, DSM_BYTES>>>(out);
}

// round 13
// speedup vs baseline: 1.9269x; 1.1076x over previous
#include <cuda_runtime.h>
#include <cuda_fp16.h>
#include <cstdint>
#include <cstddef>

#define NPTS 300000

static constexpr int kV0 = 60000, kV1 = 30000, kV2 = 15000, kV3 = 120000;
static constexpr int kTOTV = kV0 + kV1 + kV2 + kV3;            // 225000
static constexpr int kOFF0 = 0, kOFF1 = 60000, kOFF2 = 90000, kOFF3 = 105000;
static constexpr int kVIN = kV0 + kV1 + kV2;                   // 105000
static constexpr int kB = 2, kH = 512, kW = 512, kHW = kH * kW;
static constexpr int kSCB = (kTOTV + 1023) / 1024;             // 220 scan blocks

// ---------------- scratch (static device globals; no allocation) -------------
__device__ float4 g_sums[kTOTV];            // per-voxel point sums (x,y,z,w)
__device__ float  g_counts[kTOTV];          // per-voxel counts
__device__ int    g_offsets[kTOTV];         // per-scale exclusive scan of counts
__device__ int    g_cursor[kTOTV];          // fill cursors
__device__ int    g_blk[256];               // scan block totals
__device__ int    g_plist[4 * NPTS];        // CSR point lists, segmented per scale
__device__ __half g_sf1[(size_t)NPTS * 192];   // [N, 3*64] AVFE sf features (half)
__device__ __half g_vmax[(size_t)kVIN * 64];   // per-voxel max of sf, scales 0-2
__device__ __half g_sf2h[(size_t)NPTS * 128];  // [N,128] AVFEO sf (half)
__device__ __half g_wt[128 * 384];          // W_pt2 transposed to [n][k], half
__device__ float  g_omax[(size_t)kV3 * 128];   // per-voxel output max (coalesced)
__device__ int    g_occmap[kB * kHW];       // dense cell -> scale-3 voxel (-1 empty)

__device__ __forceinline__ float relu(float x) { return fmaxf(x, 0.f); }

__device__ __forceinline__ uint32_t smem_u32(const void* p) {
    uint32_t a;
    asm("{ .reg .u64 t; cvta.to.shared.u64 t, %1; cvt.u32.u64 %0, t; }"
        : "=r"(a) : "l"(p));
    return a;
}

__device__ __forceinline__ void cp_async16(uint32_t saddr, const void* gaddr,
                                           int src_bytes) {
    asm volatile("cp.async.cg.shared.global [%0], [%1], 16, %2;"
                 :: "r"(saddr), "l"(gaddr), "r"(src_bytes));
}
#define CP_COMMIT() asm volatile("cp.async.commit_group;" ::: "memory")
#define CP_WAIT(n)  asm volatile("cp.async.wait_group %0;" :: "n"(n) : "memory")

__device__ __forceinline__ void red_add_f4(float4* addr, float4 v) {
    asm volatile("red.global.add.v4.f32 [%0], {%1, %2, %3, %4};"
                 :: "l"(addr), "f"(v.x), "f"(v.y), "f"(v.z), "f"(v.w)
                 : "memory");
}

__device__ __forceinline__ void mma16816(float* c, uint32_t a0, uint32_t a1,
                                         uint32_t a2, uint32_t a3,
                                         uint32_t b0, uint32_t b1) {
    asm volatile(
        "mma.sync.aligned.m16n8k16.row.col.f32.f16.f16.f32 "
        "{%0,%1,%2,%3}, {%4,%5,%6,%7}, {%8,%9}, {%0,%1,%2,%3};"
        : "+f"(c[0]), "+f"(c[1]), "+f"(c[2]), "+f"(c[3])
        : "r"(a0), "r"(a1), "r"(a2), "r"(a3), "r"(b0), "r"(b1));
}

// ---------------- K0: zero scratch + occmap init (merged) -------------------
__global__ void k_zero() {
    int i = blockIdx.x * blockDim.x + threadIdx.x;
    if (i < kTOTV * 4) ((float*)g_sums)[i] = 0.f;
    if (i < kTOTV) { g_counts[i] = 0.f; g_cursor[i] = 0; }
    if (i < kB * kHW) g_occmap[i] = -1;
}
__global__ void k_occfill(const int* __restrict__ vfs) {
    int w = blockIdx.x * blockDim.x + threadIdx.x;
    if (w >= kV3) return;
    int vb = vfs[w * 3 + 0], vy = vfs[w * 3 + 1], vx = vfs[w * 3 + 2];
    g_occmap[vb * kHW + vy * kW + vx] = w;
}

// ---------------- K1: segment sums + counts, vector red.add -----------------
__global__ void k_accum(const float4* __restrict__ pts, const int* __restrict__ pvs) {
    int p = blockIdx.x * blockDim.x + threadIdx.x;
    if (p >= NPTS) return;
    float4 q = pts[p];
    const int off[4] = {kOFF0, kOFF1, kOFF2, kOFF3};
#pragma unroll
    for (int i = 0; i < 4; i++) {
        int b = off[i] + pvs[i * NPTS + p];
        red_add_f4(&g_sums[b], q);
        atomicAdd(&g_counts[b], 1.f);
    }
}

// ---------------- K2: global 3-phase exclusive scan of counts ---------------
__global__ __launch_bounds__(256) void k_scanA() {
    __shared__ int s[1024];
    __shared__ int warpsum[8];
    int b = blockIdx.x, tid = threadIdx.x;
    int base = b * 1024;
    for (int k = tid; k < 1024; k += 256) {
        int j = base + k;
        s[k] = (j < kTOTV) ? (int)g_counts[j] : 0;
    }
    __syncthreads();
    int e0 = s[4 * tid], e1 = s[4 * tid + 1], e2 = s[4 * tid + 2], e3 = s[4 * tid + 3];
    int tsum = e0 + e1 + e2 + e3;
    int lane = tid & 31, wid = tid >> 5;
    int x = tsum;
#pragma unroll
    for (int o = 1; o < 32; o <<= 1) {
        int y = __shfl_up_sync(~0u, x, o);
        if (lane >= o) x += y;
    }
    if (lane == 31) warpsum[wid] = x;
    __syncthreads();
    if (wid == 0) {
        int w = (lane < 8) ? warpsum[lane] : 0;
#pragma unroll
        for (int o = 1; o < 8; o <<= 1) {
            int y = __shfl_up_sync(~0u, w, o);
            if (lane >= o) w += y;
        }
        if (lane < 8) warpsum[lane] = w;   // inclusive warp totals
    }
    __syncthreads();
    int warpoff = (wid > 0) ? warpsum[wid - 1] : 0;
    int texcl = warpoff + x - tsum;        // exclusive prefix for this thread
    int j = base + 4 * tid;
    if (j < kTOTV)     g_offsets[j]     = texcl;
    texcl += e0;
    if (j + 1 < kTOTV) g_offsets[j + 1] = texcl;
    texcl += e1;
    if (j + 2 < kTOTV) g_offsets[j + 2] = texcl;
    texcl += e2;
    if (j + 3 < kTOTV) g_offsets[j + 3] = texcl;
    if (tid == 0) g_blk[b] = warpsum[7];
}

__global__ void k_scanB() {   // 1 block, 32 threads: exclusive scan of g_blk
    __shared__ int s[224];
    int tid = threadIdx.x;
    for (int k = tid; k < kSCB; k += 32) s[k] = g_blk[k];
    __syncwarp();
    int loc[7]; int sum = 0;
#pragma unroll
    for (int u = 0; u < 7; u++) {
        int k = tid * 7 + u;
        int v = (k < kSCB) ? s[k] : 0;
        loc[u] = sum; sum += v;
    }
    int x = sum;
#pragma unroll
    for (int o = 1; o < 32; o <<= 1) {
        int y = __shfl_up_sync(~0u, x, o);
        if (tid >= o) x += y;
    }
    int excl = x - sum;
#pragma unroll
    for (int u = 0; u < 7; u++) {
        int k = tid * 7 + u;
        if (k < kSCB) g_blk[k] = excl + loc[u];
    }
}

__global__ void k_scanC() {
    int j = blockIdx.x * 256 + threadIdx.x;
    if (j >= kTOTV) return;
    int sb;
    if (j < kOFF1)      sb = 0;
    else if (j < kOFF2) sb = NPTS;
    else if (j < kOFF3) sb = 2 * NPTS;
    else                sb = 3 * NPTS;
    g_offsets[j] += g_blk[j >> 10] - sb;
}

// ---------------- K3: fill CSR point lists ----------------------------------
__global__ void k_fill(const int* __restrict__ pvs) {
    int p = blockIdx.x * blockDim.x + threadIdx.x;
    if (p >= NPTS) return;
    const int off[4] = {kOFF0, kOFF1, kOFF2, kOFF3};
#pragma unroll
    for (int i = 0; i < 4; i++) {
        int b = off[i] + pvs[i * NPTS + p];
        int pos = atomicAdd(&g_cursor[b], 1);
        g_plist[i * NPTS + g_offsets[b] + pos] = p;
    }
}

// ---------------- K3b: transpose W_pt2 -> [n][k] half -----------------------
__global__ void k_prepw(const float* __restrict__ Wpt2) {
    int idx = blockIdx.x * blockDim.x + threadIdx.x;
    if (idx >= 128 * 384) return;
    int n = idx / 384, k = idx % 384;
    g_wt[idx] = __float2half(Wpt2[k * 128 + n]);
}

// ------ K4+K5 fused: AVFE compute + segment-max, voxel-major ----------------
// Warp per voxel (scales 0-2). Per-voxel mean hoisted out of the point loop.
// Per point: broadcast pts load, compute pf/af/sf in regs, write sf1 row
// (coalesced 128B, consumed later by the GEMM), keep running max in regs.
__global__ __launch_bounds__(256) void k_avfemax(
    const float4* __restrict__ pts, const float* __restrict__ Wp1,
    const float* __restrict__ Wa1) {
    __shared__ float sWp[256];   // [4][64]
    __shared__ float sWa[512];   // [8][64]
    for (int j = threadIdx.x; j < 256; j += 256) sWp[j] = Wp1[j];
    for (int j = threadIdx.x; j < 512; j += 256) sWa[j] = Wa1[j];
    __syncthreads();

    int w = blockIdx.x * 8 + (threadIdx.x >> 5);
    if (w >= kVIN) return;
    int lane = threadIdx.x & 31;
    int c0 = lane, c1 = lane + 32;
    int i;
    if (w < kV0)            i = 0;
    else if (w < kV0 + kV1) i = 1;
    else                    i = 2;
    int b = w;                        // packed global voxel index
    int o = g_offsets[b];
    int cnt = (int)g_counts[b];
    const int* pl = &g_plist[i * NPTS + o];

    float inv = 1.0f / fmaxf((float)cnt, 1.0f);
    float4 s = g_sums[b];
    float m0v = s.x * inv, m1v = s.y * inv, m2v = s.z * inv, m3v = s.w * inv;
    // mean-dependent half of af (constant per voxel)
    float afc0 = m0v * sWa[256 + c0] + m1v * sWa[320 + c0] + m2v * sWa[384 + c0] + m3v * sWa[448 + c0];
    float afc1 = m0v * sWa[256 + c1] + m1v * sWa[320 + c1] + m2v * sWa[384 + c1] + m3v * sWa[448 + c1];

    float mx0 = 0.f, mx1 = 0.f;       // sf >= 0 always
    for (int t = 0; t < cnt; t++) {
        int p = pl[t];
        float4 q = pts[p];
        float pf0 = relu(q.x * sWp[c0] + q.y * sWp[64 + c0] + q.z * sWp[128 + c0] + q.w * sWp[192 + c0]);
        float pf1 = relu(q.x * sWp[c1] + q.y * sWp[64 + c1] + q.z * sWp[128 + c1] + q.w * sWp[192 + c1]);
        float a0 = q.x - m0v, a1 = q.y - m1v, a2 = q.z - m2v, a3 = q.w;
        float af0 = a0 * sWa[c0] + a1 * sWa[64 + c0] + a2 * sWa[128 + c0] + a3 * sWa[192 + c0] + afc0;
        float af1 = a0 * sWa[c1] + a1 * sWa[64 + c1] + a2 * sWa[128 + c1] + a3 * sWa[192 + c1] + afc1;
        float sf0 = pf0 * relu(af0);
        float sf1 = pf1 * relu(af1);
        size_t fb = (size_t)p * 192 + i * 64;
        g_sf1[fb + c0] = __float2half(sf0);
        g_sf1[fb + c1] = __float2half(sf1);
        mx0 = fmaxf(mx0, sf0);
        mx1 = fmaxf(mx1, sf1);
    }
    // match precision of previous pipeline: max over half-rounded values
    g_vmax[(size_t)b * 64 + lane]      = __float2half(mx0);
    g_vmax[(size_t)b * 64 + lane + 32] = __float2half(mx1);
}

// ------ K6: HMMA GEMM  sf2 = relu(final@W_pt2) * relu(att2@W_att2) ----------
// R6-proven inner loop (scalar LDS fragments, 16x128 warp tile) + cp.async
// 2-stage double buffer: prefetch chunk c+1 (LDGSTS) while MMAs run chunk c.
static constexpr int GSTRIDE = 40;

__global__ __launch_bounds__(256) void k_gemm_mma(
    const float4* __restrict__ pts, const float* __restrict__ Watt2,
    const int* __restrict__ pvs) {
    __shared__ __align__(16) __half sA[2][128 * GSTRIDE];
    __shared__ __align__(16) __half sB[2][128 * GSTRIDE];
    __shared__ float sWs[1024];
    __shared__ int   svox[3][128];

    int tid = threadIdx.x;
    int warp = tid >> 5, lane = tid & 31;
    int p0 = blockIdx.x * 128;
    for (int j = tid; j < 1024; j += 256) sWs[j] = Watt2[j];
    for (int j = tid; j < 384; j += 256) {
        int i = j >> 7, r = j & 127;
        int p = p0 + r;
        svox[i][r] = (p < NPTS) ? pvs[i * NPTS + p] : 0;
    }
    __syncthreads();   // svox used by prefetch below
    const int voff[3] = {kOFF0, kOFF1, kOFF2};

    float acc[16][4];
#pragma unroll
    for (int nt = 0; nt < 16; nt++)
#pragma unroll
        for (int j = 0; j < 4; j++) acc[nt][j] = 0.f;

    int row0 = tid >> 2, row1 = (256 + tid) >> 2;
    int seg = tid & 3;
    uint32_t sa_base = smem_u32(sA), sb_base = smem_u32(sB);
    const int BUFB = 128 * GSTRIDE * 2;   // bytes per buffer stage

    auto issue_chunk = [&](int c, int buf) {
        int i_s = c >> 2, sub = c & 3;
#pragma unroll
        for (int it = 0; it < 2; it++) {
            int row = it ? row1 : row0;
            uint32_t sa = sa_base + buf * BUFB + (uint32_t)(row * GSTRIDE + seg * 8) * 2;
            const void* gsrc;
            int bytes = 16;
            int gp = p0 + row;
            if (sub < 2) {
                gsrc = &g_sf1[(size_t)gp * 192 + i_s * 64 + sub * 32 + seg * 8];
                if (gp >= NPTS) { gsrc = &g_sf1[0]; bytes = 0; }
            } else {
                int vox = svox[i_s][row];
                gsrc = &g_vmax[((size_t)(voff[i_s] + vox)) * 64 + (sub - 2) * 32 + seg * 8];
            }
            cp_async16(sa, gsrc, bytes);
            uint32_t sb = sb_base + buf * BUFB + (uint32_t)(row * GSTRIDE + seg * 8) * 2;
            cp_async16(sb, &g_wt[row * 384 + c * 32 + seg * 8], 16);
        }
        CP_COMMIT();
    };

    issue_chunk(0, 0);
    for (int c = 0; c < 12; c++) {
        int buf = c & 1;
        if (c < 11) issue_chunk(c + 1, buf ^ 1);
        if (c < 11) { CP_WAIT(1); } else { CP_WAIT(0); }
        __syncthreads();
        const __half* cA = sA[buf];
        const __half* cB = sB[buf];
#pragma unroll
        for (int ks = 0; ks < 2; ks++) {
            int ar = warp * 16 + (lane >> 2);
            int ac = ks * 16 + 2 * (lane & 3);
            uint32_t a0 = *(const uint32_t*)&cA[ar * GSTRIDE + ac];
            uint32_t a1 = *(const uint32_t*)&cA[(ar + 8) * GSTRIDE + ac];
            uint32_t a2 = *(const uint32_t*)&cA[ar * GSTRIDE + ac + 8];
            uint32_t a3 = *(const uint32_t*)&cA[(ar + 8) * GSTRIDE + ac + 8];
#pragma unroll
            for (int nt = 0; nt < 16; nt++) {
                int br = nt * 8 + (lane >> 2);
                int bc = ks * 16 + 2 * (lane & 3);
                uint32_t b0 = *(const uint32_t*)&cB[br * GSTRIDE + bc];
                uint32_t b1 = *(const uint32_t*)&cB[br * GSTRIDE + bc + 8];
                mma16816(acc[nt], a0, a1, a2, a3, b0, b1);
            }
        }
        __syncthreads();
    }

    // Epilogue: attention-2 + relu + half2 sf2 write
    int ra = p0 + warp * 16 + (lane >> 2);
    int rb = ra + 8;
#pragma unroll
    for (int rsel = 0; rsel < 2; rsel++) {
        int p = rsel ? rb : ra;
        if (p >= NPTS) continue;
        int b = kOFF3 + pvs[3 * NPTS + p];
        float inv = 1.0f / fmaxf(g_counts[b], 1.0f);
        float4 s = g_sums[b];
        float4 q = pts[p];
        float m0 = s.x * inv, m1 = s.y * inv, m2 = s.z * inv, m3 = s.w * inv;
        float a0 = q.x - m0, a1 = q.y - m1, a2 = q.z - m2, a3 = q.w;
#pragma unroll
        for (int nt = 0; nt < 16; nt++) {
            int c = nt * 8 + 2 * (lane & 3);
            float af0 = a0 * sWs[c] + a1 * sWs[128 + c] + a2 * sWs[256 + c]
                      + a3 * sWs[384 + c] + m0 * sWs[512 + c] + m1 * sWs[640 + c]
                      + m2 * sWs[768 + c] + m3 * sWs[896 + c];
            int c1 = c + 1;
            float af1 = a0 * sWs[c1] + a1 * sWs[128 + c1] + a2 * sWs[256 + c1]
                      + a3 * sWs[384 + c1] + m0 * sWs[512 + c1] + m1 * sWs[640 + c1]
                      + m2 * sWs[768 + c1] + m3 * sWs[896 + c1];
            float v0 = relu(acc[nt][rsel * 2 + 0]) * relu(af0);
            float v1 = relu(acc[nt][rsel * 2 + 1]) * relu(af1);
            *(__half2*)&g_sf2h[(size_t)p * 128 + c] = __floats2half2_rn(v0, v1);
        }
    }
}

// ------ K7: segment-max over sf2 (scale 3) -> g_omax (coalesced write) ------
__global__ __launch_bounds__(256) void k_vmax3() {
    int w = blockIdx.x * 8 + (threadIdx.x >> 5);
    if (w >= kV3) return;
    int lane = threadIdx.x & 31;
    int b = kOFF3 + w;
    int o = g_offsets[b];
    int cnt = (int)g_counts[b];
    const int* pl = &g_plist[3 * NPTS + o];
    float m0 = 0.f, m1 = 0.f, m2 = 0.f, m3 = 0.f;
    for (int t = 0; t < cnt; t++) {
        int pt = pl[t];
        size_t sb = (size_t)pt * 128 + lane;
        m0 = fmaxf(m0, __half2float(g_sf2h[sb]));
        m1 = fmaxf(m1, __half2float(g_sf2h[sb + 32]));
        m2 = fmaxf(m2, __half2float(g_sf2h[sb + 64]));
        m3 = fmaxf(m3, __half2float(g_sf2h[sb + 96]));
    }
    size_t ob = (size_t)w * 128;
    g_omax[ob + lane]      = m0;
    g_omax[ob + lane + 32] = m1;
    g_omax[ob + lane + 64] = m2;
    g_omax[ob + lane + 96] = m3;
}

// ------ K8: dense output writer, one (b,y) row per block --------------------
static constexpr int DCAP = 200;
static constexpr int DSM_BYTES = 512 * 4 + DCAP * 4 + 16 + DCAP * 129 * 4;

__global__ __launch_bounds__(256) void k_dense(float* __restrict__ out) {
    extern __shared__ char dsm[];
    int*   s_sidx = (int*)dsm;                       // [512]
    int*   s_vox  = (int*)(dsm + 2048);              // [DCAP]
    int*   s_cnt  = (int*)(dsm + 2048 + DCAP * 4);   // [1]
    float* s_om   = (float*)(dsm + 2048 + DCAP * 4 + 16); // [DCAP*129]

    int row = blockIdx.x;            // 0..kB*kH-1
    int b = row >> 9, y = row & 511;
    int tid = threadIdx.x;
    if (tid == 0) *s_cnt = 0;
    __syncthreads();

    int cellbase = b * kHW + y * kW;
    for (int x = tid; x < 512; x += 256) {
        int v = g_occmap[cellbase + x];
        int code = -1;
        if (v >= 0) {
            int slot = atomicAdd(s_cnt, 1);
            if (slot < DCAP) { s_vox[slot] = v; code = slot; }
            else             { code = -2 - v; }   // overflow: direct gather
        }
        s_sidx[x] = code;
    }
    __syncthreads();
    int cnt = min(*s_cnt, DCAP);
    for (int j = tid; j < cnt * 128; j += 256) {
        int slot = j >> 7, c = j & 127;
        s_om[slot * 129 + c] = g_omax[(size_t)s_vox[slot] * 128 + c];
    }
    __syncthreads();

    size_t outbase = ((size_t)b * 128) * kHW + (size_t)y * kW;
#pragma unroll 4
    for (int c = 0; c < 128; c++) {
        size_t ob = outbase + (size_t)c * kHW;
        for (int x = tid; x < 512; x += 256) {
            int code = s_sidx[x];
            float val = 0.f;
            if (code >= 0)       val = s_om[code * 129 + c];
            else if (code <= -2) val = g_omax[(size_t)(-2 - code) * 128 + c];
            out[ob + x] = val;
        }
    }
}

// ---------------------------------------------------------------------------
extern "C" void kernel_launch(void* const* d_in, const int* in_sizes, int n_in,
                              void* d_out, int out_size) {
    const float4* pts   = (const float4*)d_in[0];
    const float*  Wp1   = (const float*)d_in[1];
    const float*  Wa1   = (const float*)d_in[2];
    const float*  Wpt2  = (const float*)d_in[3];
    const float*  Watt2 = (const float*)d_in[4];
    const int*    pvs   = (const int*)d_in[5];
    const int*    vfs   = (const int*)d_in[6];
    float*        out   = (float*)d_out;

    cudaFuncSetAttribute(k_dense, cudaFuncAttributeMaxDynamicSharedMemorySize,
                         DSM_BYTES);

    k_zero<<<(kTOTV * 4 + 255) / 256, 256>>>();
    k_occfill<<<(kV3 + 255) / 256, 256>>>(vfs);
    k_accum<<<(NPTS + 255) / 256, 256>>>(pts, pvs);
    k_scanA<<<kSCB, 256>>>();
    k_scanB<<<1, 32>>>();
    k_scanC<<<(kTOTV + 255) / 256, 256>>>();
    k_fill<<<(NPTS + 255) / 256, 256>>>(pvs);
    k_prepw<<<(128 * 384 + 255) / 256, 256>>>(Wpt2);
    k_avfemax<<<(kVIN + 7) / 8, 256>>>(pts, Wp1, Wa1);
    k_gemm_mma<<<(NPTS + 127) / 128, 256>>>(pts, Watt2, pvs);
    k_vmax3<<<(kV3 + 7) / 8, 256>>>();
    k_dense<<<kB * kH, 256, DSM_BYTES>>>(out);
}

// round 14
// speedup vs baseline: 1.9468x; 1.0104x over previous
#include <cuda_runtime.h>
#include <cuda_fp16.h>
#include <cstdint>
#include <cstddef>

#define NPTS 300000

static constexpr int kV0 = 60000, kV1 = 30000, kV2 = 15000, kV3 = 120000;
static constexpr int kTOTV = kV0 + kV1 + kV2 + kV3;            // 225000
static constexpr int kOFF0 = 0, kOFF1 = 60000, kOFF2 = 90000, kOFF3 = 105000;
static constexpr int kVIN = kV0 + kV1 + kV2;                   // 105000
static constexpr int kB = 2, kH = 512, kW = 512, kHW = kH * kW;
static constexpr int kSCB = (kTOTV + 1023) / 1024;             // 220 scan blocks

// ---------------- scratch (static device globals; no allocation) -------------
__device__ float4 g_sums[kTOTV];            // per-voxel point sums (x,y,z,w)
__device__ float  g_counts[kTOTV];          // per-voxel counts
__device__ int    g_offsets[kTOTV];         // per-scale exclusive scan of counts
__device__ int    g_cursor[kTOTV];          // fill cursors
__device__ int    g_blk[256];               // scan block totals
__device__ int    g_plist[4 * NPTS];        // CSR point lists, segmented per scale
__device__ __half g_sf1[(size_t)NPTS * 192];   // [N, 3*64] AVFE sf features (half)
__device__ __half g_vmax[(size_t)kVIN * 64];   // per-voxel max of sf, scales 0-2
__device__ __half g_sf2h[(size_t)NPTS * 128];  // [N,128] AVFEO sf, PERMUTED by plist3
__device__ __half g_wt[128 * 384];          // W_pt2 transposed to [n][k], half
__device__ float  g_omax[(size_t)kV3 * 128];   // per-voxel output max (coalesced)
__device__ int    g_occmap[kB * kHW];       // dense cell -> scale-3 voxel (-1 empty)

__device__ __forceinline__ float relu(float x) { return fmaxf(x, 0.f); }

__device__ __forceinline__ uint32_t smem_u32(const void* p) {
    uint32_t a;
    asm("{ .reg .u64 t; cvta.to.shared.u64 t, %1; cvt.u32.u64 %0, t; }"
        : "=r"(a) : "l"(p));
    return a;
}

__device__ __forceinline__ void cp_async16(uint32_t saddr, const void* gaddr,
                                           int src_bytes) {
    asm volatile("cp.async.cg.shared.global [%0], [%1], 16, %2;"
                 :: "r"(saddr), "l"(gaddr), "r"(src_bytes));
}
#define CP_COMMIT() asm volatile("cp.async.commit_group;" ::: "memory")
#define CP_WAIT(n)  asm volatile("cp.async.wait_group %0;" :: "n"(n) : "memory")

__device__ __forceinline__ void red_add_f4(float4* addr, float4 v) {
    asm volatile("red.global.add.v4.f32 [%0], {%1, %2, %3, %4};"
                 :: "l"(addr), "f"(v.x), "f"(v.y), "f"(v.z), "f"(v.w)
                 : "memory");
}

__device__ __forceinline__ void mma16816(float* c, uint32_t a0, uint32_t a1,
                                         uint32_t a2, uint32_t a3,
                                         uint32_t b0, uint32_t b1) {
    asm volatile(
        "mma.sync.aligned.m16n8k16.row.col.f32.f16.f16.f32 "
        "{%0,%1,%2,%3}, {%4,%5,%6,%7}, {%8,%9}, {%0,%1,%2,%3};"
        : "+f"(c[0]), "+f"(c[1]), "+f"(c[2]), "+f"(c[3])
        : "r"(a0), "r"(a1), "r"(a2), "r"(a3), "r"(b0), "r"(b1));
}

// ---------------- K0: zero scratch + occmap init (merged) -------------------
__global__ void k_zero() {
    int i = blockIdx.x * blockDim.x + threadIdx.x;
    if (i < kTOTV * 4) ((float*)g_sums)[i] = 0.f;
    if (i < kTOTV) { g_counts[i] = 0.f; g_cursor[i] = 0; }
    if (i < kB * kHW) g_occmap[i] = -1;
}
__global__ void k_occfill(const int* __restrict__ vfs) {
    int w = blockIdx.x * blockDim.x + threadIdx.x;
    if (w >= kV3) return;
    int vb = vfs[w * 3 + 0], vy = vfs[w * 3 + 1], vx = vfs[w * 3 + 2];
    g_occmap[vb * kHW + vy * kW + vx] = w;
}

// ---------------- K1: segment sums + counts, vector red.add -----------------
__global__ void k_accum(const float4* __restrict__ pts, const int* __restrict__ pvs) {
    int p = blockIdx.x * blockDim.x + threadIdx.x;
    if (p >= NPTS) return;
    float4 q = pts[p];
    const int off[4] = {kOFF0, kOFF1, kOFF2, kOFF3};
#pragma unroll
    for (int i = 0; i < 4; i++) {
        int b = off[i] + pvs[i * NPTS + p];
        red_add_f4(&g_sums[b], q);
        atomicAdd(&g_counts[b], 1.f);
    }
}

// ---------------- K2: global 3-phase exclusive scan of counts ---------------
__global__ __launch_bounds__(256) void k_scanA() {
    __shared__ int s[1024];
    __shared__ int warpsum[8];
    int b = blockIdx.x, tid = threadIdx.x;
    int base = b * 1024;
    for (int k = tid; k < 1024; k += 256) {
        int j = base + k;
        s[k] = (j < kTOTV) ? (int)g_counts[j] : 0;
    }
    __syncthreads();
    int e0 = s[4 * tid], e1 = s[4 * tid + 1], e2 = s[4 * tid + 2], e3 = s[4 * tid + 3];
    int tsum = e0 + e1 + e2 + e3;
    int lane = tid & 31, wid = tid >> 5;
    int x = tsum;
#pragma unroll
    for (int o = 1; o < 32; o <<= 1) {
        int y = __shfl_up_sync(~0u, x, o);
        if (lane >= o) x += y;
    }
    if (lane == 31) warpsum[wid] = x;
    __syncthreads();
    if (wid == 0) {
        int w = (lane < 8) ? warpsum[lane] : 0;
#pragma unroll
        for (int o = 1; o < 8; o <<= 1) {
            int y = __shfl_up_sync(~0u, w, o);
            if (lane >= o) w += y;
        }
        if (lane < 8) warpsum[lane] = w;   // inclusive warp totals
    }
    __syncthreads();
    int warpoff = (wid > 0) ? warpsum[wid - 1] : 0;
    int texcl = warpoff + x - tsum;        // exclusive prefix for this thread
    int j = base + 4 * tid;
    if (j < kTOTV)     g_offsets[j]     = texcl;
    texcl += e0;
    if (j + 1 < kTOTV) g_offsets[j + 1] = texcl;
    texcl += e1;
    if (j + 2 < kTOTV) g_offsets[j + 2] = texcl;
    texcl += e2;
    if (j + 3 < kTOTV) g_offsets[j + 3] = texcl;
    if (tid == 0) g_blk[b] = warpsum[7];
}

__global__ void k_scanB() {   // 1 block, 32 threads: exclusive scan of g_blk
    __shared__ int s[224];
    int tid = threadIdx.x;
    for (int k = tid; k < kSCB; k += 32) s[k] = g_blk[k];
    __syncwarp();
    int loc[7]; int sum = 0;
#pragma unroll
    for (int u = 0; u < 7; u++) {
        int k = tid * 7 + u;
        int v = (k < kSCB) ? s[k] : 0;
        loc[u] = sum; sum += v;
    }
    int x = sum;
#pragma unroll
    for (int o = 1; o < 32; o <<= 1) {
        int y = __shfl_up_sync(~0u, x, o);
        if (tid >= o) x += y;
    }
    int excl = x - sum;
#pragma unroll
    for (int u = 0; u < 7; u++) {
        int k = tid * 7 + u;
        if (k < kSCB) g_blk[k] = excl + loc[u];
    }
}

__global__ void k_scanC() {
    int j = blockIdx.x * 256 + threadIdx.x;
    if (j >= kTOTV) return;
    int sb;
    if (j < kOFF1)      sb = 0;
    else if (j < kOFF2) sb = NPTS;
    else if (j < kOFF3) sb = 2 * NPTS;
    else                sb = 3 * NPTS;
    g_offsets[j] += g_blk[j >> 10] - sb;
}

// ---------------- K3: fill CSR point lists ----------------------------------
__global__ void k_fill(const int* __restrict__ pvs) {
    int p = blockIdx.x * blockDim.x + threadIdx.x;
    if (p >= NPTS) return;
    const int off[4] = {kOFF0, kOFF1, kOFF2, kOFF3};
#pragma unroll
    for (int i = 0; i < 4; i++) {
        int b = off[i] + pvs[i * NPTS + p];
        int pos = atomicAdd(&g_cursor[b], 1);
        g_plist[i * NPTS + g_offsets[b] + pos] = p;
    }
}

// ---------------- K3b: transpose W_pt2 -> [n][k] half -----------------------
__global__ void k_prepw(const float* __restrict__ Wpt2) {
    int idx = blockIdx.x * blockDim.x + threadIdx.x;
    if (idx >= 128 * 384) return;
    int n = idx / 384, k = idx % 384;
    g_wt[idx] = __float2half(Wpt2[k * 128 + n]);
}

// ------ K4+K5 fused: AVFE compute + segment-max, voxel-major ----------------
__global__ __launch_bounds__(256) void k_avfemax(
    const float4* __restrict__ pts, const float* __restrict__ Wp1,
    const float* __restrict__ Wa1) {
    __shared__ float sWp[256];   // [4][64]
    __shared__ float sWa[512];   // [8][64]
    for (int j = threadIdx.x; j < 256; j += 256) sWp[j] = Wp1[j];
    for (int j = threadIdx.x; j < 512; j += 256) sWa[j] = Wa1[j];
    __syncthreads();

    int w = blockIdx.x * 8 + (threadIdx.x >> 5);
    if (w >= kVIN) return;
    int lane = threadIdx.x & 31;
    int c0 = lane, c1 = lane + 32;
    int i;
    if (w < kV0)            i = 0;
    else if (w < kV0 + kV1) i = 1;
    else                    i = 2;
    int b = w;                        // packed global voxel index
    int o = g_offsets[b];
    int cnt = (int)g_counts[b];
    const int* pl = &g_plist[i * NPTS + o];

    float inv = 1.0f / fmaxf((float)cnt, 1.0f);
    float4 s = g_sums[b];
    float m0v = s.x * inv, m1v = s.y * inv, m2v = s.z * inv, m3v = s.w * inv;
    float afc0 = m0v * sWa[256 + c0] + m1v * sWa[320 + c0] + m2v * sWa[384 + c0] + m3v * sWa[448 + c0];
    float afc1 = m0v * sWa[256 + c1] + m1v * sWa[320 + c1] + m2v * sWa[384 + c1] + m3v * sWa[448 + c1];

    float mx0 = 0.f, mx1 = 0.f;       // sf >= 0 always
    for (int t = 0; t < cnt; t++) {
        int p = pl[t];
        float4 q = pts[p];
        float pf0 = relu(q.x * sWp[c0] + q.y * sWp[64 + c0] + q.z * sWp[128 + c0] + q.w * sWp[192 + c0]);
        float pf1 = relu(q.x * sWp[c1] + q.y * sWp[64 + c1] + q.z * sWp[128 + c1] + q.w * sWp[192 + c1]);
        float a0 = q.x - m0v, a1 = q.y - m1v, a2 = q.z - m2v, a3 = q.w;
        float af0 = a0 * sWa[c0] + a1 * sWa[64 + c0] + a2 * sWa[128 + c0] + a3 * sWa[192 + c0] + afc0;
        float af1 = a0 * sWa[c1] + a1 * sWa[64 + c1] + a2 * sWa[128 + c1] + a3 * sWa[192 + c1] + afc1;
        float sf0 = pf0 * relu(af0);
        float sf1 = pf1 * relu(af1);
        size_t fb = (size_t)p * 192 + i * 64;
        g_sf1[fb + c0] = __float2half(sf0);
        g_sf1[fb + c1] = __float2half(sf1);
        mx0 = fmaxf(mx0, sf0);
        mx1 = fmaxf(mx1, sf1);
    }
    g_vmax[(size_t)b * 64 + lane]      = __float2half(mx0);
    g_vmax[(size_t)b * 64 + lane + 32] = __float2half(mx1);
}

// ------ K6: HMMA GEMM, rows PERMUTED by scale-3 CSR order -------------------
// Row j of the GEMM corresponds to point plist3[j]; sf2h written at row j so
// each scale-3 voxel's rows are contiguous for the streaming max (k_vmax3).
// A-tile loads gather via splist (cp.async double-buffered — latency hidden).
static constexpr int GSTRIDE = 40;

__global__ __launch_bounds__(256) void k_gemm_mma(
    const float4* __restrict__ pts, const float* __restrict__ Watt2,
    const int* __restrict__ pvs) {
    __shared__ __align__(16) __half sA[2][128 * GSTRIDE];
    __shared__ __align__(16) __half sB[2][128 * GSTRIDE];
    __shared__ float sWs[1024];
    __shared__ int   svox[3][128];
    __shared__ int   splist[128];

    int tid = threadIdx.x;
    int warp = tid >> 5, lane = tid & 31;
    int p0 = blockIdx.x * 128;
    for (int j = tid; j < 1024; j += 256) sWs[j] = Watt2[j];
    if (tid < 128) {
        int jj = p0 + tid;
        splist[tid] = (jj < NPTS) ? g_plist[3 * NPTS + jj] : -1;
    }
    __syncthreads();   // splist needed below
    for (int j = tid; j < 384; j += 256) {
        int i = j >> 7, r = j & 127;
        int ps = splist[r];
        svox[i][r] = (ps >= 0) ? pvs[i * NPTS + ps] : 0;
    }
    __syncthreads();
    const int voff[3] = {kOFF0, kOFF1, kOFF2};

    float acc[16][4];
#pragma unroll
    for (int nt = 0; nt < 16; nt++)
#pragma unroll
        for (int j = 0; j < 4; j++) acc[nt][j] = 0.f;

    int row0 = tid >> 2, row1 = (256 + tid) >> 2;
    int seg = tid & 3;
    uint32_t sa_base = smem_u32(sA), sb_base = smem_u32(sB);
    const int BUFB = 128 * GSTRIDE * 2;   // bytes per buffer stage

    auto issue_chunk = [&](int c, int buf) {
        int i_s = c >> 2, sub = c & 3;
#pragma unroll
        for (int it = 0; it < 2; it++) {
            int row = it ? row1 : row0;
            int ps = splist[row];
            uint32_t sa = sa_base + buf * BUFB + (uint32_t)(row * GSTRIDE + seg * 8) * 2;
            const void* gsrc;
            int bytes = 16;
            if (sub < 2) {
                gsrc = &g_sf1[(size_t)(ps < 0 ? 0 : ps) * 192 + i_s * 64 + sub * 32 + seg * 8];
                if (ps < 0) bytes = 0;
            } else {
                int vox = svox[i_s][row];
                gsrc = &g_vmax[((size_t)(voff[i_s] + vox)) * 64 + (sub - 2) * 32 + seg * 8];
            }
            cp_async16(sa, gsrc, bytes);
            uint32_t sb = sb_base + buf * BUFB + (uint32_t)(row * GSTRIDE + seg * 8) * 2;
            cp_async16(sb, &g_wt[row * 384 + c * 32 + seg * 8], 16);
        }
        CP_COMMIT();
    };

    issue_chunk(0, 0);
    for (int c = 0; c < 12; c++) {
        int buf = c & 1;
        if (c < 11) issue_chunk(c + 1, buf ^ 1);
        if (c < 11) { CP_WAIT(1); } else { CP_WAIT(0); }
        __syncthreads();
        const __half* cA = sA[buf];
        const __half* cB = sB[buf];
#pragma unroll
        for (int ks = 0; ks < 2; ks++) {
            int ar = warp * 16 + (lane >> 2);
            int ac = ks * 16 + 2 * (lane & 3);
            uint32_t a0 = *(const uint32_t*)&cA[ar * GSTRIDE + ac];
            uint32_t a1 = *(const uint32_t*)&cA[(ar + 8) * GSTRIDE + ac];
            uint32_t a2 = *(const uint32_t*)&cA[ar * GSTRIDE + ac + 8];
            uint32_t a3 = *(const uint32_t*)&cA[(ar + 8) * GSTRIDE + ac + 8];
#pragma unroll
            for (int nt = 0; nt < 16; nt++) {
                int br = nt * 8 + (lane >> 2);
                int bc = ks * 16 + 2 * (lane & 3);
                uint32_t b0 = *(const uint32_t*)&cB[br * GSTRIDE + bc];
                uint32_t b1 = *(const uint32_t*)&cB[br * GSTRIDE + bc + 8];
                mma16816(acc[nt], a0, a1, a2, a3, b0, b1);
            }
        }
        __syncthreads();
    }

    // Epilogue: attention-2 + relu + half2 sf2 write at PERMUTED row j
    int rowa = warp * 16 + (lane >> 2);
#pragma unroll
    for (int rsel = 0; rsel < 2; rsel++) {
        int row = rowa + rsel * 8;
        int j = p0 + row;
        if (j >= NPTS) continue;
        int p = splist[row];
        int b = kOFF3 + pvs[3 * NPTS + p];
        float inv = 1.0f / fmaxf(g_counts[b], 1.0f);
        float4 s = g_sums[b];
        float4 q = pts[p];
        float m0 = s.x * inv, m1 = s.y * inv, m2 = s.z * inv, m3 = s.w * inv;
        float a0 = q.x - m0, a1 = q.y - m1, a2 = q.z - m2, a3 = q.w;
#pragma unroll
        for (int nt = 0; nt < 16; nt++) {
            int c = nt * 8 + 2 * (lane & 3);
            float af0 = a0 * sWs[c] + a1 * sWs[128 + c] + a2 * sWs[256 + c]
                      + a3 * sWs[384 + c] + m0 * sWs[512 + c] + m1 * sWs[640 + c]
                      + m2 * sWs[768 + c] + m3 * sWs[896 + c];
            int c1 = c + 1;
            float af1 = a0 * sWs[c1] + a1 * sWs[128 + c1] + a2 * sWs[256 + c1]
                      + a3 * sWs[384 + c1] + m0 * sWs[512 + c1] + m1 * sWs[640 + c1]
                      + m2 * sWs[768 + c1] + m3 * sWs[896 + c1];
            float v0 = relu(acc[nt][rsel * 2 + 0]) * relu(af0);
            float v1 = relu(acc[nt][rsel * 2 + 1]) * relu(af1);
            *(__half2*)&g_sf2h[(size_t)j * 128 + c] = __floats2half2_rn(v0, v1);
        }
    }
}

// ------ K7: streaming segment-max over permuted sf2 -> g_omax ---------------
// Voxel w owns contiguous sf2h rows [offsets[b], offsets[b]+cnt). Coalesced.
__global__ __launch_bounds__(256) void k_vmax3() {
    int w = blockIdx.x * 8 + (threadIdx.x >> 5);
    if (w >= kV3) return;
    int lane = threadIdx.x & 31;
    int b = kOFF3 + w;
    int o = g_offsets[b];
    int cnt = (int)g_counts[b];
    float m0 = 0.f, m1 = 0.f, m2 = 0.f, m3 = 0.f;
    const __half* base = &g_sf2h[(size_t)o * 128];
    for (int t = 0; t < cnt; t++) {
        const __half* row = base + (size_t)t * 128;
        m0 = fmaxf(m0, __half2float(row[lane]));
        m1 = fmaxf(m1, __half2float(row[lane + 32]));
        m2 = fmaxf(m2, __half2float(row[lane + 64]));
        m3 = fmaxf(m3, __half2float(row[lane + 96]));
    }
    size_t ob = (size_t)w * 128;
    g_omax[ob + lane]      = m0;
    g_omax[ob + lane + 32] = m1;
    g_omax[ob + lane + 64] = m2;
    g_omax[ob + lane + 96] = m3;
}

// ------ K8: dense output writer, one (b,y) row per block --------------------
static constexpr int DCAP = 200;
static constexpr int DSM_BYTES = 512 * 4 + DCAP * 4 + 16 + DCAP * 129 * 4;

__global__ __launch_bounds__(256) void k_dense(float* __restrict__ out) {
    extern __shared__ char dsm[];
    int*   s_sidx = (int*)dsm;                       // [512]
    int*   s_vox  = (int*)(dsm + 2048);              // [DCAP]
    int*   s_cnt  = (int*)(dsm + 2048 + DCAP * 4);   // [1]
    float* s_om   = (float*)(dsm + 2048 + DCAP * 4 + 16); // [DCAP*129]

    int row = blockIdx.x;            // 0..kB*kH-1
    int b = row >> 9, y = row & 511;
    int tid = threadIdx.x;
    if (tid == 0) *s_cnt = 0;
    __syncthreads();

    int cellbase = b * kHW + y * kW;
    for (int x = tid; x < 512; x += 256) {
        int v = g_occmap[cellbase + x];
        int code = -1;
        if (v >= 0) {
            int slot = atomicAdd(s_cnt, 1);
            if (slot < DCAP) { s_vox[slot] = v; code = slot; }
            else             { code = -2 - v; }   // overflow: direct gather
        }
        s_sidx[x] = code;
    }
    __syncthreads();
    int cnt = min(*s_cnt, DCAP);
    for (int j = tid; j < cnt * 128; j += 256) {
        int slot = j >> 7, c = j & 127;
        s_om[slot * 129 + c] = g_omax[(size_t)s_vox[slot] * 128 + c];
    }
    __syncthreads();

    size_t outbase = ((size_t)b * 128) * kHW + (size_t)y * kW;
#pragma unroll 4
    for (int c = 0; c < 128; c++) {
        size_t ob = outbase + (size_t)c * kHW;
        for (int x = tid; x < 512; x += 256) {
            int code = s_sidx[x];
            float val = 0.f;
            if (code >= 0)       val = s_om[code * 129 + c];
            else if (code <= -2) val = g_omax[(size_t)(-2 - code) * 128 + c];
            out[ob + x] = val;
        }
    }
}

// ---------------------------------------------------------------------------
extern "C" void kernel_launch(void* const* d_in, const int* in_sizes, int n_in,
                              void* d_out, int out_size) {
    const float4* pts   = (const float4*)d_in[0];
    const float*  Wp1   = (const float*)d_in[1];
    const float*  Wa1   = (const float*)d_in[2];
    const float*  Wpt2  = (const float*)d_in[3];
    const float*  Watt2 = (const float*)d_in[4];
    const int*    pvs   = (const int*)d_in[5];
    const int*    vfs   = (const int*)d_in[6];
    float*        out   = (float*)d_out;

    cudaFuncSetAttribute(k_dense, cudaFuncAttributeMaxDynamicSharedMemorySize,
                         DSM_BYTES);

    k_zero<<<(kTOTV * 4 + 255) / 256, 256>>>();
    k_occfill<<<(kV3 + 255) / 256, 256>>>(vfs);
    k_accum<<<(NPTS + 255) / 256, 256>>>(pts, pvs);
    k_scanA<<<kSCB, 256>>>();
    k_scanB<<<1, 32>>>();
    k_scanC<<<(kTOTV + 255) / 256, 256>>>();
    k_fill<<<(NPTS + 255) / 256, 256>>>(pvs);
    k_prepw<<<(128 * 384 + 255) / 256, 256>>>(Wpt2);
    k_avfemax<<<(kVIN + 7) / 8, 256>>>(pts, Wp1, Wa1);
    k_gemm_mma<<<(NPTS + 127) / 128, 256>>>(pts, Watt2, pvs);
    k_vmax3<<<(kV3 + 7) / 8, 256>>>();
    k_dense<<<kB * kH, 256, DSM_BYTES>>>(out);
}